// round 7
// baseline (speedup 1.0000x reference)
#include <cuda_runtime.h>
#include <cuda_bf16.h>
#include <math.h>

#define NSEQ 256
#define CZ   128
#define NH   4
#define HD   32
#define RTOT (NSEQ * NSEQ)

typedef unsigned int u32;
typedef unsigned long long u64;

// ---------------- global scratch ----------------
__device__ __nv_bfloat16 g_Qhi[(size_t)RTOT * CZ];
__device__ __nv_bfloat16 g_Qlo[(size_t)RTOT * CZ];
__device__ __nv_bfloat16 g_Khi[(size_t)RTOT * CZ];
__device__ __nv_bfloat16 g_Klo[(size_t)RTOT * CZ];
__device__ __nv_bfloat16 g_Vhi[(size_t)RTOT * CZ];
__device__ __nv_bfloat16 g_Vlo[(size_t)RTOT * CZ];
__device__ float g_G[(size_t)RTOT * CZ];
__device__ float g_BiasT[(size_t)NH * RTOT];
__device__ float g_AV[(size_t)RTOT * CZ];
__device__ __nv_bfloat16 g_WtHi[5][CZ * CZ];
__device__ __nv_bfloat16 g_WtLo[5][CZ * CZ];

// ---------------- helpers ----------------
__device__ __forceinline__ u32 smem_u32(const void* p) {
    u32 a;
    asm("{ .reg .u64 t; cvta.to.shared.u64 t, %1; cvt.u32.u64 %0, t; }" : "=r"(a) : "l"(p));
    return a;
}
__device__ __forceinline__ void ldsm_x4(u32* r, u32 addr) {
    asm volatile("ldmatrix.sync.aligned.m8n8.x4.shared.b16 {%0,%1,%2,%3}, [%4];"
        : "=r"(r[0]), "=r"(r[1]), "=r"(r[2]), "=r"(r[3]) : "r"(addr));
}
__device__ __forceinline__ void ldsm_x4_t(u32* r, u32 addr) {
    asm volatile("ldmatrix.sync.aligned.m8n8.x4.trans.shared.b16 {%0,%1,%2,%3}, [%4];"
        : "=r"(r[0]), "=r"(r[1]), "=r"(r[2]), "=r"(r[3]) : "r"(addr));
}
__device__ __forceinline__ void mma_bf16(float* d, const u32* a, const u32* b) {
    asm volatile("mma.sync.aligned.m16n8k16.row.col.f32.bf16.bf16.f32 "
        "{%0,%1,%2,%3}, {%4,%5,%6,%7}, {%8,%9}, {%0,%1,%2,%3};"
        : "+f"(d[0]), "+f"(d[1]), "+f"(d[2]), "+f"(d[3])
        : "r"(a[0]), "r"(a[1]), "r"(a[2]), "r"(a[3]), "r"(b[0]), "r"(b[1]));
}
__device__ __forceinline__ u32 pack_bf2(float x, float y) {
    __nv_bfloat162 t;
    t.x = __float2bfloat16(x);
    t.y = __float2bfloat16(y);
    return *(u32*)&t;
}
__device__ __forceinline__ void split_pack(float x, float y, u32& h, u32& l) {
    __nv_bfloat16 hx = __float2bfloat16(x);
    __nv_bfloat16 hy = __float2bfloat16(y);
    __nv_bfloat162 hh; hh.x = hx; hh.y = hy;
    h = *(u32*)&hh;
    l = pack_bf2(x - __bfloat162float(hx), y - __bfloat162float(hy));
}
__device__ __forceinline__ void cp16(u32 dst, const void* src) {
    u64 g;
    asm("cvta.to.global.u64 %0, %1;" : "=l"(g) : "l"(src));
    asm volatile("cp.async.ca.shared.global [%0], [%1], 16;" :: "r"(dst), "l"(g));
}
__device__ __forceinline__ void prefetch_l1(const void* p) {
    asm volatile("prefetch.global.L1 [%0];" :: "l"(p));
}
#define CP_COMMIT() asm volatile("cp.async.commit_group;")
#define CP_WAIT(n)  asm volatile("cp.async.wait_group %0;" :: "n"(n))

#define TSTRIDE 136
#define THALF   34816

// lnproj smem
#define LNP_SA   0
#define LNP_SB0  69632
#define LNP_SB1  139264
#define LNP_XS   69632
#define LNP_WB   (69632 + 66048)
#define LNP_SMEM 208896
// outproj smem (64-row tiles)
#define OP_AHALF 17408
#define OP_SA    0
#define OP_SB    34816
#define OP_SMEM  104448

// ---------------------------------------------------------------------------
// Kernel 0: transpose + hi/lo-split weights
// ---------------------------------------------------------------------------
__global__ void wtransform(const float* __restrict__ Wq, const float* __restrict__ Wk,
                           const float* __restrict__ Wv, const float* __restrict__ Wg,
                           const float* __restrict__ Wo)
{
    const float* W = (blockIdx.x == 0) ? Wq : (blockIdx.x == 1) ? Wk :
                     (blockIdx.x == 2) ? Wv : (blockIdx.x == 3) ? Wg : Wo;
    __nv_bfloat16* H = g_WtHi[blockIdx.x];
    __nv_bfloat16* L = g_WtLo[blockIdx.x];
    for (int e = threadIdx.x; e < CZ * CZ; e += blockDim.x) {
        int n = e >> 7, c = e & 127;
        float a = W[c * CZ + n];
        __nv_bfloat16 hi = __float2bfloat16(a);
        H[e] = hi;
        L[e] = __float2bfloat16(a - __bfloat162float(hi));
    }
}

// ---------------------------------------------------------------------------
// Pipelined GEMM warp mainloop: 16 rows x 64 cols; depth-1 reg double-buffer
// ---------------------------------------------------------------------------
__device__ __forceinline__ void gemm_warp(float acc[8][4], u32 aBase, u32 aHalf, u32 bBase)
{
    u32 ah[2][4], al[2][4], bh[2][4], bl[2][4];
    ldsm_x4(ah[0], aBase);
    ldsm_x4(al[0], aBase + aHalf);
    ldsm_x4(bh[0], bBase);
    ldsm_x4(bl[0], bBase + THALF);
#pragma unroll
    for (int ks = 0; ks < 8; ks++) {
        const int ak = ks & 1;
        if (ks < 7) {   // prefetch next ks's A fragments (4 steps early)
            ldsm_x4(ah[ak ^ 1], aBase + (ks + 1) * 32);
            ldsm_x4(al[ak ^ 1], aBase + aHalf + (ks + 1) * 32);
        }
#pragma unroll
        for (int p = 0; p < 4; p++) {
            const int cur = (ks * 4 + p) & 1, nxt = cur ^ 1;
            if (!(ks == 7 && p == 3)) {   // prefetch next step's B fragments
                const int nks = (p == 3) ? ks + 1 : ks;
                const int np  = (p == 3) ? 0 : p + 1;
                u32 ba = bBase + (u32)(np * 16 * TSTRIDE) * 2 + nks * 32;
                ldsm_x4(bh[nxt], ba);
                ldsm_x4(bl[nxt], ba + THALF);
            }
            mma_bf16(acc[2 * p],     ah[ak], bh[cur]);
            mma_bf16(acc[2 * p + 1], ah[ak], bh[cur] + 2);
            mma_bf16(acc[2 * p],     al[ak], bh[cur]);
            mma_bf16(acc[2 * p + 1], al[ak], bh[cur] + 2);
            mma_bf16(acc[2 * p],     ah[ak], bl[cur]);
            mma_bf16(acc[2 * p + 1], ah[ak], bl[cur] + 2);
        }
    }
}

__device__ __forceinline__ void cp_weights(u32 sb, u32 bufOff, int m, int tid, int nthr)
{
    for (int e = tid; e < 4096; e += nthr) {
        int half = e >> 11, rem = e & 2047, n = rem >> 4, ch = rem & 15;
        const __nv_bfloat16* src = (half ? g_WtLo[m] : g_WtHi[m]) + n * 128 + ch * 8;
        u32 dst = sb + bufOff + (u32)half * THALF + (u32)(n * TSTRIDE + ch * 8) * 2;
        cp16(dst, src);
    }
    CP_COMMIT();
}

// ---------------------------------------------------------------------------
// Kernel 1: LN + Q/K/V/G projections; Q/K/V written split-bf16 (Q pre-scaled)
// ---------------------------------------------------------------------------
__global__ __launch_bounds__(512) void lnproj_mma(const float* __restrict__ x,
                                                  const float* __restrict__ gamma,
                                                  const float* __restrict__ beta,
                                                  const float* __restrict__ Wb,
                                                  const float* __restrict__ bg)
{
    extern __shared__ char sm[];
    const u32 sb = smem_u32(sm);
    const int tid = threadIdx.x, wid = tid >> 5, lane = tid & 31;
    const int wr = wid & 7, wc = wid >> 3;
    const size_t r0 = (size_t)blockIdx.x * 128;
    float* xs  = (float*)(sm + LNP_XS);
    float* sWb = (float*)(sm + LNP_WB);

    const float4* xg = (const float4*)(x + r0 * CZ);
    for (int i = tid; i < 4096; i += 512) {
        float4 v = xg[i];
        int row = i >> 5, c = (i & 31) << 2;
        float* d = xs + row * 129 + c;
        d[0] = v.x; d[1] = v.y; d[2] = v.z; d[3] = v.w;
    }
    sWb[tid] = Wb[tid];
    __syncthreads();

    // LayerNorm: 4 threads per row, quad shuffles
    {
        int row = tid >> 2, sub = tid & 3;
        float* rp = xs + row * 129;
        float s = 0.f, s2 = 0.f;
#pragma unroll
        for (int c = sub * 32; c < sub * 32 + 32; c++) { float v = rp[c]; s += v; s2 += v * v; }
        s  += __shfl_xor_sync(0xFFFFFFFF, s, 1);
        s  += __shfl_xor_sync(0xFFFFFFFF, s, 2);
        s2 += __shfl_xor_sync(0xFFFFFFFF, s2, 1);
        s2 += __shfl_xor_sync(0xFFFFFFFF, s2, 2);
        float mu  = s * (1.f / 128.f);
        float var = s2 * (1.f / 128.f) - mu * mu;
        float inv = rsqrtf(var + 1e-5f);
#pragma unroll
        for (int c = sub * 32; c < sub * 32 + 32; c++)
            rp[c] = (rp[c] - mu) * inv * __ldg(gamma + c) + __ldg(beta + c);
    }
    __syncthreads();

    {
        int row = tid >> 2, h = tid & 3;
        const float* xr = xs + row * 129;
        float s = 0.f;
#pragma unroll 8
        for (int c = 0; c < 128; c++) s += xr[c] * sWb[c * 4 + h];
        g_BiasT[(size_t)h * RTOT + r0 + row] = s;
    }
    for (int p = tid; p < 8192; p += 512) {
        int row = p >> 6, c = (p & 63) << 1;
        u32 hh, ll;
        split_pack(xs[row * 129 + c], xs[row * 129 + c + 1], hh, ll);
        u32 off = (u32)(row * TSTRIDE + c) * 2;
        *(u32*)(sm + LNP_SA + off)         = hh;
        *(u32*)(sm + LNP_SA + THALF + off) = ll;
    }
    cp_weights(sb, LNP_SB1, 0, tid, 512);
    __syncthreads();

    const int i_ = lane >> 3, r_ = lane & 7;
    const u32 aBase = sb + LNP_SA +
        (u32)((wr * 16 + ((i_ & 1) << 3) + r_) * TSTRIDE + ((i_ >> 1) << 3)) * 2;
    const u32 bOffW = (u32)((wc * 64 + ((i_ >> 1) << 3) + r_) * TSTRIDE + ((i_ & 1) << 3)) * 2;
    const int g = lane >> 2, tig = lane & 3;
    const size_t rowA = r0 + wr * 16 + g;
    const size_t rowB = rowA + 8;

#pragma unroll
    for (int m = 0; m < 4; m++) {
        if (m < 3) cp_weights(sb, (m & 1) ? LNP_SB1 : LNP_SB0, m + 1, tid, 512);
        if (m < 3) { CP_WAIT(1); } else { CP_WAIT(0); }
        __syncthreads();

        const u32 bufOff = (m & 1) ? LNP_SB0 : LNP_SB1;
        float acc[8][4];
#pragma unroll
        for (int t = 0; t < 8; t++)
#pragma unroll
            for (int v = 0; v < 4; v++) acc[t][v] = 0.f;

        gemm_warp(acc, aBase, THALF, sb + bufOff + bOffW);

        if (m < 3) {
            __nv_bfloat16* Ohi = (m == 0) ? g_Qhi : (m == 1) ? g_Khi : g_Vhi;
            __nv_bfloat16* Olo = (m == 0) ? g_Qlo : (m == 1) ? g_Klo : g_Vlo;
            const float qs = (m == 0) ? 0.17677669529663689f : 1.f;
#pragma unroll
            for (int nt = 0; nt < 8; nt++) {
                int col = wc * 64 + nt * 8 + tig * 2;
                u32 hA, lA, hB, lB;
                split_pack(acc[nt][0] * qs, acc[nt][1] * qs, hA, lA);
                split_pack(acc[nt][2] * qs, acc[nt][3] * qs, hB, lB);
                *(u32*)(Ohi + rowA * CZ + col) = hA;
                *(u32*)(Olo + rowA * CZ + col) = lA;
                *(u32*)(Ohi + rowB * CZ + col) = hB;
                *(u32*)(Olo + rowB * CZ + col) = lB;
            }
        } else {
#pragma unroll
            for (int nt = 0; nt < 8; nt++) {
                int col = wc * 64 + nt * 8 + tig * 2;
                float2 bgv = __ldg((const float2*)(bg + col));
                float2 oA, oB;
                oA.x = 1.f / (1.f + __expf(-(acc[nt][0] + bgv.x)));
                oA.y = 1.f / (1.f + __expf(-(acc[nt][1] + bgv.y)));
                oB.x = 1.f / (1.f + __expf(-(acc[nt][2] + bgv.x)));
                oB.y = 1.f / (1.f + __expf(-(acc[nt][3] + bgv.y)));
                *(float2*)(g_G + rowA * CZ + col) = oA;
                *(float2*)(g_G + rowB * CZ + col) = oB;
            }
        }
        __syncthreads();
    }
}

// ---------------------------------------------------------------------------
// Kernel 2: attention. Pipelined QK ldsm; PV ldsm-before-pack; L1 bias prefetch.
// ---------------------------------------------------------------------------
#define KSTR 40
#define AT_BUF 20480
#define AT_SMEM (4 * AT_BUF)

__global__ __launch_bounds__(256, 2) void attn_mma()
{
    extern __shared__ char sm[];
    const u32 sb = smem_u32(sm);
    const int tid = threadIdx.x, wid = tid >> 5, lane = tid & 31;
    const int bi = blockIdx.x;
    const int h  = blockIdx.y >> 1;
    const int jh = blockIdx.y & 1;
    const size_t base = ((size_t)bi * NSEQ) * CZ + (size_t)h * HD;

    for (int e = tid; e < 4096; e += 256) {
        int buf = e >> 10, rem = e & 1023, k = rem >> 2, ch = rem & 3;
        const __nv_bfloat16* src =
            ((buf == 0) ? g_Khi : (buf == 1) ? g_Klo : (buf == 2) ? g_Vhi : g_Vlo)
            + base + (size_t)k * CZ + ch * 8;
        u32 dst = sb + (u32)buf * AT_BUF + (u32)(k * KSTR + ch * 8) * 2;
        cp16(dst, src);
    }
    CP_COMMIT();

    const int jr = jh * 128 + wid * 16;
    const int r  = lane >> 2, c2 = (lane & 3) << 1;

    u32 qhi[2][4], qlo[2][4];
#pragma unroll
    for (int ks = 0; ks < 2; ks++)
#pragma unroll
        for (int reg = 0; reg < 4; reg++) {
            int row = jr + r + (reg & 1) * 8;
            int col = ks * 16 + c2 + ((reg >> 1) << 3);
            qhi[ks][reg] = *(const u32*)(g_Qhi + base + (size_t)row * CZ + col);
            qlo[ks][reg] = *(const u32*)(g_Qlo + base + (size_t)row * CZ + col);
        }

    CP_WAIT(0);
    __syncthreads();

    const int i_ = lane >> 3, r_ = lane & 7;
    const int brow = ((i_ >> 1) << 3) + r_;
    const int bcol = (i_ & 1) << 3;
    const int vsel = lane >> 3, vrow = lane & 7;
    const u32 vOff = (u32)(((vsel & 1) * 8 + vrow) * KSTR + ((vsel >> 1) << 3)) * 2;

    float oacc[4][4];
#pragma unroll
    for (int t = 0; t < 4; t++)
#pragma unroll
        for (int v = 0; v < 4; v++) oacc[t][v] = 0.f;
    float lsum0 = 0.f, lsum1 = 0.f;

    const float* bias0 = g_BiasT + (size_t)h * RTOT + (size_t)(jr + r) * NSEQ;
    const float* bias1 = bias0 + 8 * NSEQ;

    for (int kc = 0; kc < 4; kc++) {
        // L1 prefetch of this kc's bias lines (consumed after the 48-MMA block)
#pragma unroll
        for (int nt = 0; nt < 8; nt += 2) {
            prefetch_l1(bias0 + kc * 64 + nt * 8 + c2);
            prefetch_l1(bias1 + kc * 64 + nt * 8 + c2);
        }

        float sacc[8][4];
#pragma unroll
        for (int t = 0; t < 8; t++)
#pragma unroll
            for (int v = 0; v < 4; v++) sacc[t][v] = 0.f;

        // ---- S = Q K^T, depth-1 pipelined ldsm ----
        {
            u32 kh[2][4], kl[2][4];
            u32 a0 = sb + (u32)((kc * 64 + brow) * KSTR + bcol) * 2;
            ldsm_x4(kh[0], a0);
            ldsm_x4(kl[0], a0 + AT_BUF);
#pragma unroll
            for (int s = 0; s < 8; s++) {
                const int p4 = s >> 1, ks = s & 1;
                const int cur = s & 1, nxt = cur ^ 1;
                if (s < 7) {
                    const int ns = s + 1, np4 = ns >> 1, nks = ns & 1;
                    u32 addr = sb + (u32)((kc * 64 + np4 * 16 + brow) * KSTR + nks * 16 + bcol) * 2;
                    ldsm_x4(kh[nxt], addr);
                    ldsm_x4(kl[nxt], addr + AT_BUF);
                }
                mma_bf16(sacc[2 * p4],     qhi[ks], kh[cur]);
                mma_bf16(sacc[2 * p4 + 1], qhi[ks], kh[cur] + 2);
                mma_bf16(sacc[2 * p4],     qlo[ks], kh[cur]);
                mma_bf16(sacc[2 * p4 + 1], qlo[ks], kh[cur] + 2);
                mma_bf16(sacc[2 * p4],     qhi[ks], kl[cur]);
                mma_bf16(sacc[2 * p4 + 1], qhi[ks], kl[cur] + 2);
            }
        }

        // ---- bias + exp (no-max; scores bounded) ----
#pragma unroll
        for (int nt = 0; nt < 8; nt++) {
            int kcol = kc * 64 + nt * 8 + c2;
            float2 b0 = __ldg((const float2*)(bias0 + kcol));
            float2 b1 = __ldg((const float2*)(bias1 + kcol));
            float p00 = __expf(sacc[nt][0] + b0.x);
            float p01 = __expf(sacc[nt][1] + b0.y);
            float p10 = __expf(sacc[nt][2] + b1.x);
            float p11 = __expf(sacc[nt][3] + b1.y);
            sacc[nt][0] = p00; sacc[nt][1] = p01;
            sacc[nt][2] = p10; sacc[nt][3] = p11;
            lsum0 += p00 + p01;
            lsum1 += p10 + p11;
        }

        // ---- O += P V: ldsm first (latency covered by split packs), then mma ----
#pragma unroll
        for (int ks2 = 0; ks2 < 4; ks2++) {
            u32 a0 = sb + 2u * AT_BUF + (u32)((kc * 64 + ks2 * 16) * KSTR) * 2 + vOff;
            u32 vh[8], vl[8];
            ldsm_x4_t(vh,     a0);
            ldsm_x4_t(vh + 4, a0 + 32);
            ldsm_x4_t(vl,     a0 + AT_BUF);
            ldsm_x4_t(vl + 4, a0 + AT_BUF + 32);
            u32 phi[4], plo[4];
            {
                const float* s0 = sacc[2 * ks2];
                const float* s1 = sacc[2 * ks2 + 1];
                split_pack(s0[0], s0[1], phi[0], plo[0]);
                split_pack(s0[2], s0[3], phi[1], plo[1]);
                split_pack(s1[0], s1[1], phi[2], plo[2]);
                split_pack(s1[2], s1[3], phi[3], plo[3]);
            }
#pragma unroll
            for (int ntd = 0; ntd < 4; ntd++) {
                mma_bf16(oacc[ntd], phi, vh + 2 * ntd);
                mma_bf16(oacc[ntd], plo, vh + 2 * ntd);
                mma_bf16(oacc[ntd], phi, vl + 2 * ntd);
            }
        }
    }

    lsum0 += __shfl_xor_sync(0xFFFFFFFF, lsum0, 1);
    lsum0 += __shfl_xor_sync(0xFFFFFFFF, lsum0, 2);
    lsum1 += __shfl_xor_sync(0xFFFFFFFF, lsum1, 1);
    lsum1 += __shfl_xor_sync(0xFFFFFFFF, lsum1, 2);
    const float inv0 = __fdividef(1.f, lsum0);
    const float inv1 = __fdividef(1.f, lsum1);

    const size_t row0 = base + (size_t)(jr + r) * CZ;
    const size_t row1 = row0 + 8 * CZ;
#pragma unroll
    for (int ntd = 0; ntd < 4; ntd++) {
        int col = ntd * 8 + c2;
        float2 g0 = __ldg((const float2*)(g_G + row0 + col));
        float2 g1 = __ldg((const float2*)(g_G + row1 + col));
        float2 o0, o1;
        o0.x = oacc[ntd][0] * inv0 * g0.x;
        o0.y = oacc[ntd][1] * inv0 * g0.y;
        o1.x = oacc[ntd][2] * inv1 * g1.x;
        o1.y = oacc[ntd][3] * inv1 * g1.y;
        *(float2*)(g_AV + row0 + col) = o0;
        *(float2*)(g_AV + row1 + col) = o1;
    }
}

// ---------------------------------------------------------------------------
// Kernel 3: output projection, 64-row CTAs, pipelined mainloop
// ---------------------------------------------------------------------------
__global__ __launch_bounds__(256, 2) void outproj_mma(const float* __restrict__ bo_,
                                                      float* __restrict__ out)
{
    extern __shared__ char sm[];
    const u32 sb = smem_u32(sm);
    const int tid = threadIdx.x, wid = tid >> 5, lane = tid & 31;
    const int wr = wid & 3, wc = wid >> 2;
    const size_t r0 = (size_t)blockIdx.x * 64;

    cp_weights(sb, OP_SB, 4, tid, 256);

    for (int p = tid; p < 4096; p += 256) {
        int row = p >> 6, c = (p & 63) << 1;
        float2 v = *(const float2*)(g_AV + (r0 + row) * CZ + c);
        u32 hh, ll;
        split_pack(v.x, v.y, hh, ll);
        u32 off = (u32)(row * TSTRIDE + c) * 2;
        *(u32*)(sm + OP_SA + off)            = hh;
        *(u32*)(sm + OP_SA + OP_AHALF + off) = ll;
    }
    CP_WAIT(0);
    __syncthreads();

    const int i_ = lane >> 3, r_ = lane & 7;
    const u32 aBase = sb + OP_SA +
        (u32)((wr * 16 + ((i_ & 1) << 3) + r_) * TSTRIDE + ((i_ >> 1) << 3)) * 2;
    const u32 bBase = sb + OP_SB +
        (u32)((wc * 64 + ((i_ >> 1) << 3) + r_) * TSTRIDE + ((i_ & 1) << 3)) * 2;

    float acc[8][4];
#pragma unroll
    for (int t = 0; t < 8; t++)
#pragma unroll
        for (int v = 0; v < 4; v++) acc[t][v] = 0.f;

    gemm_warp(acc, aBase, OP_AHALF, bBase);

    const int g = lane >> 2, tig = lane & 3;
    const size_t rowA = r0 + wr * 16 + g;
    const size_t rowB = rowA + 8;
#pragma unroll
    for (int nt = 0; nt < 8; nt++) {
        int col = wc * 64 + nt * 8 + tig * 2;
        float2 bov = __ldg((const float2*)(bo_ + col));
        *(float2*)(out + rowA * CZ + col) = make_float2(acc[nt][0] + bov.x, acc[nt][1] + bov.y);
        *(float2*)(out + rowB * CZ + col) = make_float2(acc[nt][2] + bov.x, acc[nt][3] + bov.y);
    }
}

// ---------------------------------------------------------------------------
extern "C" void kernel_launch(void* const* d_in, const int* in_sizes, int n_in,
                              void* d_out, int out_size)
{
    const float* x     = (const float*)d_in[0];
    const float* gamma = (const float*)d_in[1];
    const float* beta  = (const float*)d_in[2];
    const float* Wq    = (const float*)d_in[3];
    const float* Wk    = (const float*)d_in[4];
    const float* Wv    = (const float*)d_in[5];
    const float* Wb    = (const float*)d_in[6];
    const float* Wg    = (const float*)d_in[7];
    const float* bg    = (const float*)d_in[8];
    const float* Wo    = (const float*)d_in[9];
    const float* bo    = (const float*)d_in[10];
    float* out = (float*)d_out;

    cudaFuncSetAttribute(lnproj_mma,  cudaFuncAttributeMaxDynamicSharedMemorySize, LNP_SMEM);
    cudaFuncSetAttribute(outproj_mma, cudaFuncAttributeMaxDynamicSharedMemorySize, OP_SMEM);
    cudaFuncSetAttribute(attn_mma,    cudaFuncAttributeMaxDynamicSharedMemorySize, AT_SMEM);

    wtransform<<<5, 256>>>(Wq, Wk, Wv, Wg, Wo);
    lnproj_mma<<<RTOT / 128, 512, LNP_SMEM>>>(x, gamma, beta, Wb, bg);
    dim3 g2(NSEQ, 2 * NH);
    attn_mma<<<g2, 256, AT_SMEM>>>();
    outproj_mma<<<RTOT / 64, 256, OP_SMEM>>>(bo, out);
}

// round 8
// speedup vs baseline: 1.2912x; 1.2912x over previous
#include <cuda_runtime.h>
#include <cuda_fp16.h>
#include <math.h>

#define NSEQ 256
#define CZ   128
#define NH   4
#define HD   32
#define RTOT (NSEQ * NSEQ)

typedef unsigned int u32;
typedef unsigned long long u64;

// ---------------- global scratch ----------------
// Q split fp16 (pre-scaled); K/V single fp16; weights single fp16 transposed
__device__ __half g_Qhi[(size_t)RTOT * CZ];
__device__ __half g_Qlo[(size_t)RTOT * CZ];
__device__ __half g_Kh[(size_t)RTOT * CZ];
__device__ __half g_Vh[(size_t)RTOT * CZ];
__device__ float  g_G[(size_t)RTOT * CZ];
__device__ float  g_BiasT[(size_t)NH * RTOT];
__device__ float  g_AV[(size_t)RTOT * CZ];
__device__ __half g_Wt[5][CZ * CZ];

// ---------------- helpers ----------------
__device__ __forceinline__ u32 smem_u32(const void* p) {
    u32 a;
    asm("{ .reg .u64 t; cvta.to.shared.u64 t, %1; cvt.u32.u64 %0, t; }" : "=r"(a) : "l"(p));
    return a;
}
__device__ __forceinline__ void ldsm_x4(u32* r, u32 addr) {
    asm volatile("ldmatrix.sync.aligned.m8n8.x4.shared.b16 {%0,%1,%2,%3}, [%4];"
        : "=r"(r[0]), "=r"(r[1]), "=r"(r[2]), "=r"(r[3]) : "r"(addr));
}
__device__ __forceinline__ void ldsm_x4_t(u32* r, u32 addr) {
    asm volatile("ldmatrix.sync.aligned.m8n8.x4.trans.shared.b16 {%0,%1,%2,%3}, [%4];"
        : "=r"(r[0]), "=r"(r[1]), "=r"(r[2]), "=r"(r[3]) : "r"(addr));
}
__device__ __forceinline__ void mma_f16(float* d, const u32* a, const u32* b) {
    asm volatile("mma.sync.aligned.m16n8k16.row.col.f32.f16.f16.f32 "
        "{%0,%1,%2,%3}, {%4,%5,%6,%7}, {%8,%9}, {%0,%1,%2,%3};"
        : "+f"(d[0]), "+f"(d[1]), "+f"(d[2]), "+f"(d[3])
        : "r"(a[0]), "r"(a[1]), "r"(a[2]), "r"(a[3]), "r"(b[0]), "r"(b[1]));
}
__device__ __forceinline__ u32 pack_h2(float x, float y) {
    __half2 t;
    t.x = __float2half_rn(x);
    t.y = __float2half_rn(y);
    return *(u32*)&t;
}
__device__ __forceinline__ void split_pack(float x, float y, u32& h, u32& l) {
    __half hx = __float2half_rn(x);
    __half hy = __float2half_rn(y);
    __half2 hh; hh.x = hx; hh.y = hy;
    h = *(u32*)&hh;
    l = pack_h2(x - __half2float(hx), y - __half2float(hy));
}
__device__ __forceinline__ void cp16(u32 dst, const void* src) {
    u64 g;
    asm("cvta.to.global.u64 %0, %1;" : "=l"(g) : "l"(src));
    asm volatile("cp.async.ca.shared.global [%0], [%1], 16;" :: "r"(dst), "l"(g));
}
#define CP_COMMIT() asm volatile("cp.async.commit_group;")
#define CP_WAIT(n)  asm volatile("cp.async.wait_group %0;" :: "n"(n))

#define TSTRIDE 136
#define TBUF    34816     // 128 rows * 136 * 2B (one fp16 tile)

// lnproj smem: A hi|lo (69632) | B buf0 (34816) | B buf1 (34816) | Wb (2048)
#define LNP_SA   0
#define LNP_SB0  69632
#define LNP_SB1  104448
#define LNP_XS   69632    // fp32 x-tile (66048) overlays SB0+SB1
#define LNP_WB   139264
#define LNP_SMEM 141312
// outproj smem (64-row tiles): A hi|lo (34816) | B (34816)
#define OP_AHALF 17408
#define OP_SA    0
#define OP_SB    34816
#define OP_SMEM  69632

// ---------------------------------------------------------------------------
// Kernel 0: transpose weights -> fp16: Wt[n][k] = W[k][n]
// ---------------------------------------------------------------------------
__global__ void wtransform(const float* __restrict__ Wq, const float* __restrict__ Wk,
                           const float* __restrict__ Wv, const float* __restrict__ Wg,
                           const float* __restrict__ Wo)
{
    const float* W = (blockIdx.x == 0) ? Wq : (blockIdx.x == 1) ? Wk :
                     (blockIdx.x == 2) ? Wv : (blockIdx.x == 3) ? Wg : Wo;
    __half* H = g_Wt[blockIdx.x];
    for (int e = threadIdx.x; e < CZ * CZ; e += blockDim.x) {
        int n = e >> 7, c = e & 127;
        H[e] = __float2half_rn(W[c * CZ + n]);
    }
}

// ---------------------------------------------------------------------------
// GEMM warp mainloop: 16 rows x 64 cols; A split (hi/lo), B single fp16.
// 4 MMAs per (ks, p) step. 128 MMAs total.
// ---------------------------------------------------------------------------
__device__ __forceinline__ void gemm_warp(float acc[8][4], u32 aBase, u32 aHalf, u32 bBase)
{
#pragma unroll
    for (int ks = 0; ks < 8; ks++) {
        u32 ah[4], al[4];
        ldsm_x4(ah, aBase + ks * 32);
        ldsm_x4(al, aBase + aHalf + ks * 32);
#pragma unroll
        for (int p = 0; p < 4; p++) {
            u32 bh[4];
            ldsm_x4(bh, bBase + (u32)(p * 16 * TSTRIDE) * 2 + ks * 32);
            mma_f16(acc[2 * p],     ah, bh);
            mma_f16(acc[2 * p + 1], ah, bh + 2);
            mma_f16(acc[2 * p],     al, bh);
            mma_f16(acc[2 * p + 1], al, bh + 2);
        }
    }
}

// async-copy one fp16 weight matrix into smem buffer
__device__ __forceinline__ void cp_weights(u32 sb, u32 bufOff, int m, int tid, int nthr)
{
    for (int e = tid; e < 2048; e += nthr) {
        int n = e >> 4, ch = e & 15;
        const __half* src = g_Wt[m] + n * 128 + ch * 8;
        cp16(sb + bufOff + (u32)(n * TSTRIDE + ch * 8) * 2, src);
    }
    CP_COMMIT();
}

// ---------------------------------------------------------------------------
// Kernel 1: LN + Q/K/V/G projections (fp16 2-term) + bias projection
// ---------------------------------------------------------------------------
__global__ __launch_bounds__(512) void lnproj_mma(const float* __restrict__ x,
                                                  const float* __restrict__ gamma,
                                                  const float* __restrict__ beta,
                                                  const float* __restrict__ Wb,
                                                  const float* __restrict__ bg)
{
    extern __shared__ char sm[];
    const u32 sb = smem_u32(sm);
    const int tid = threadIdx.x, wid = tid >> 5, lane = tid & 31;
    const int wr = wid & 7, wc = wid >> 3;
    const size_t r0 = (size_t)blockIdx.x * 128;
    float* xs  = (float*)(sm + LNP_XS);
    float* sWb = (float*)(sm + LNP_WB);

    const float4* xg = (const float4*)(x + r0 * CZ);
    for (int i = tid; i < 4096; i += 512) {
        float4 v = xg[i];
        int row = i >> 5, c = (i & 31) << 2;
        float* d = xs + row * 129 + c;
        d[0] = v.x; d[1] = v.y; d[2] = v.z; d[3] = v.w;
    }
    sWb[tid] = Wb[tid];
    __syncthreads();

    // LayerNorm: 4 threads per row, quad shuffles
    {
        int row = tid >> 2, sub = tid & 3;
        float* rp = xs + row * 129;
        float s = 0.f, s2 = 0.f;
#pragma unroll
        for (int c = sub * 32; c < sub * 32 + 32; c++) { float v = rp[c]; s += v; s2 += v * v; }
        s  += __shfl_xor_sync(0xFFFFFFFF, s, 1);
        s  += __shfl_xor_sync(0xFFFFFFFF, s, 2);
        s2 += __shfl_xor_sync(0xFFFFFFFF, s2, 1);
        s2 += __shfl_xor_sync(0xFFFFFFFF, s2, 2);
        float mu  = s * (1.f / 128.f);
        float var = s2 * (1.f / 128.f) - mu * mu;
        float inv = rsqrtf(var + 1e-5f);
#pragma unroll
        for (int c = sub * 32; c < sub * 32 + 32; c++)
            rp[c] = (rp[c] - mu) * inv * __ldg(gamma + c) + __ldg(beta + c);
    }
    __syncthreads();

    // bias projection (fp32 exact)
    {
        int row = tid >> 2, h = tid & 3;
        const float* xr = xs + row * 129;
        float s = 0.f;
#pragma unroll 8
        for (int c = 0; c < 128; c++) s += xr[c] * sWb[c * 4 + h];
        g_BiasT[(size_t)h * RTOT + r0 + row] = s;
    }
    // convert A -> split fp16 in smem (SA does not overlap xs)
    for (int p = tid; p < 8192; p += 512) {
        int row = p >> 6, c = (p & 63) << 1;
        u32 hh, ll;
        split_pack(xs[row * 129 + c], xs[row * 129 + c + 1], hh, ll);
        u32 off = (u32)(row * TSTRIDE + c) * 2;
        *(u32*)(sm + LNP_SA + off)        = hh;
        *(u32*)(sm + LNP_SA + TBUF + off) = ll;
    }
    __syncthreads();   // xs fully consumed before weights overwrite its region

    cp_weights(sb, LNP_SB0, 0, tid, 512);

    const int i_ = lane >> 3, r_ = lane & 7;
    const u32 aBase = sb + LNP_SA +
        (u32)((wr * 16 + ((i_ & 1) << 3) + r_) * TSTRIDE + ((i_ >> 1) << 3)) * 2;
    const u32 bOffW = (u32)((wc * 64 + ((i_ >> 1) << 3) + r_) * TSTRIDE + ((i_ & 1) << 3)) * 2;
    const int g = lane >> 2, tig = lane & 3;
    const size_t rowA = r0 + wr * 16 + g;
    const size_t rowB = rowA + 8;

#pragma unroll
    for (int m = 0; m < 4; m++) {
        if (m < 3) cp_weights(sb, (m & 1) ? LNP_SB0 : LNP_SB1, m + 1, tid, 512);
        if (m < 3) { CP_WAIT(1); } else { CP_WAIT(0); }
        __syncthreads();

        const u32 bufOff = (m & 1) ? LNP_SB1 : LNP_SB0;
        float acc[8][4];
#pragma unroll
        for (int t = 0; t < 8; t++)
#pragma unroll
            for (int v = 0; v < 4; v++) acc[t][v] = 0.f;

        gemm_warp(acc, aBase, TBUF, sb + bufOff + bOffW);

        if (m == 0) {
            // Q: split fp16, pre-scaled
            const float qs = 0.17677669529663689f;
#pragma unroll
            for (int nt = 0; nt < 8; nt++) {
                int col = wc * 64 + nt * 8 + tig * 2;
                u32 hA, lA, hB, lB;
                split_pack(acc[nt][0] * qs, acc[nt][1] * qs, hA, lA);
                split_pack(acc[nt][2] * qs, acc[nt][3] * qs, hB, lB);
                *(u32*)(g_Qhi + rowA * CZ + col) = hA;
                *(u32*)(g_Qlo + rowA * CZ + col) = lA;
                *(u32*)(g_Qhi + rowB * CZ + col) = hB;
                *(u32*)(g_Qlo + rowB * CZ + col) = lB;
            }
        } else if (m < 3) {
            __half* O = (m == 1) ? g_Kh : g_Vh;
#pragma unroll
            for (int nt = 0; nt < 8; nt++) {
                int col = wc * 64 + nt * 8 + tig * 2;
                *(u32*)(O + rowA * CZ + col) = pack_h2(acc[nt][0], acc[nt][1]);
                *(u32*)(O + rowB * CZ + col) = pack_h2(acc[nt][2], acc[nt][3]);
            }
        } else {
#pragma unroll
            for (int nt = 0; nt < 8; nt++) {
                int col = wc * 64 + nt * 8 + tig * 2;
                float2 bgv = __ldg((const float2*)(bg + col));
                float2 oA, oB;
                oA.x = 1.f / (1.f + __expf(-(acc[nt][0] + bgv.x)));
                oA.y = 1.f / (1.f + __expf(-(acc[nt][1] + bgv.y)));
                oB.x = 1.f / (1.f + __expf(-(acc[nt][2] + bgv.x)));
                oB.y = 1.f / (1.f + __expf(-(acc[nt][3] + bgv.y)));
                *(float2*)(g_G + rowA * CZ + col) = oA;
                *(float2*)(g_G + rowB * CZ + col) = oB;
            }
        }
        __syncthreads();
    }
}

// ---------------------------------------------------------------------------
// Kernel 2: attention. Q split / K single; P split / V single. fp16 2-term.
// Grid (256, 8): blockIdx.x = i, blockIdx.y = h*2 + jhalf. 8 warps x 16 j-rows.
// ---------------------------------------------------------------------------
#define KSTR 40
#define AT_BUF 20480      // 256 * 40 * 2
#define AT_SMEM (2 * AT_BUF)

__global__ __launch_bounds__(256, 2) void attn_mma()
{
    extern __shared__ char sm[];
    const u32 sb = smem_u32(sm);
    const int tid = threadIdx.x, wid = tid >> 5, lane = tid & 31;
    const int bi = blockIdx.x;
    const int h  = blockIdx.y >> 1;
    const int jh = blockIdx.y & 1;
    const size_t base = ((size_t)bi * NSEQ) * CZ + (size_t)h * HD;

    // stage Kh | Vh rows [256][32] fp16 via cp.async
    for (int e = tid; e < 2048; e += 256) {
        int buf = e >> 10, rem = e & 1023, k = rem >> 2, ch = rem & 3;
        const __half* src = ((buf == 0) ? g_Kh : g_Vh) + base + (size_t)k * CZ + ch * 8;
        cp16(sb + (u32)buf * AT_BUF + (u32)(k * KSTR + ch * 8) * 2, src);
    }
    CP_COMMIT();

    const int jr = jh * 128 + wid * 16;
    const int r  = lane >> 2, c2 = (lane & 3) << 1;

    // Q fragments (pre-scaled, pre-split)
    u32 qhi[2][4], qlo[2][4];
#pragma unroll
    for (int ks = 0; ks < 2; ks++)
#pragma unroll
        for (int reg = 0; reg < 4; reg++) {
            int row = jr + r + (reg & 1) * 8;
            int col = ks * 16 + c2 + ((reg >> 1) << 3);
            qhi[ks][reg] = *(const u32*)(g_Qhi + base + (size_t)row * CZ + col);
            qlo[ks][reg] = *(const u32*)(g_Qlo + base + (size_t)row * CZ + col);
        }

    CP_WAIT(0);
    __syncthreads();

    const int i_ = lane >> 3, r_ = lane & 7;
    const int brow = ((i_ >> 1) << 3) + r_;
    const int bcol = (i_ & 1) << 3;
    const int vsel = lane >> 3, vrow = lane & 7;
    const u32 vOff = (u32)(((vsel & 1) * 8 + vrow) * KSTR + ((vsel >> 1) << 3)) * 2;

    float oacc[4][4];
#pragma unroll
    for (int t = 0; t < 4; t++)
#pragma unroll
        for (int v = 0; v < 4; v++) oacc[t][v] = 0.f;
    float lsum0 = 0.f, lsum1 = 0.f;

    const float* bias0 = g_BiasT + (size_t)h * RTOT + (size_t)(jr + r) * NSEQ;
    const float* bias1 = bias0 + 8 * NSEQ;

    for (int kc = 0; kc < 4; kc++) {
        float sacc[8][4];
#pragma unroll
        for (int t = 0; t < 8; t++)
#pragma unroll
            for (int v = 0; v < 4; v++) sacc[t][v] = 0.f;

        // ---- S = Q K^T : Q split (2 terms), K single ----
#pragma unroll
        for (int p4 = 0; p4 < 4; p4++) {
#pragma unroll
            for (int ks = 0; ks < 2; ks++) {
                u32 kh[4];
                ldsm_x4(kh, sb + (u32)((kc * 64 + p4 * 16 + brow) * KSTR + ks * 16 + bcol) * 2);
                mma_f16(sacc[2 * p4],     qhi[ks], kh);
                mma_f16(sacc[2 * p4 + 1], qhi[ks], kh + 2);
                mma_f16(sacc[2 * p4],     qlo[ks], kh);
                mma_f16(sacc[2 * p4 + 1], qlo[ks], kh + 2);
            }
        }

        // ---- bias + exp (no-max; scores bounded) ----
#pragma unroll
        for (int nt = 0; nt < 8; nt++) {
            int kcol = kc * 64 + nt * 8 + c2;
            float2 b0 = __ldg((const float2*)(bias0 + kcol));
            float2 b1 = __ldg((const float2*)(bias1 + kcol));
            float p00 = __expf(sacc[nt][0] + b0.x);
            float p01 = __expf(sacc[nt][1] + b0.y);
            float p10 = __expf(sacc[nt][2] + b1.x);
            float p11 = __expf(sacc[nt][3] + b1.y);
            sacc[nt][0] = p00; sacc[nt][1] = p01;
            sacc[nt][2] = p10; sacc[nt][3] = p11;
            lsum0 += p00 + p01;
            lsum1 += p10 + p11;
        }

        // ---- O += P V : P split (2 terms), V single (trans-ldsm) ----
#pragma unroll
        for (int ks2 = 0; ks2 < 4; ks2++) {
            u32 a0 = sb + AT_BUF + (u32)((kc * 64 + ks2 * 16) * KSTR) * 2 + vOff;
            u32 vh[8];
            ldsm_x4_t(vh,     a0);
            ldsm_x4_t(vh + 4, a0 + 32);
            u32 phi[4], plo[4];
            {
                const float* s0 = sacc[2 * ks2];
                const float* s1 = sacc[2 * ks2 + 1];
                split_pack(s0[0], s0[1], phi[0], plo[0]);
                split_pack(s0[2], s0[3], phi[1], plo[1]);
                split_pack(s1[0], s1[1], phi[2], plo[2]);
                split_pack(s1[2], s1[3], phi[3], plo[3]);
            }
#pragma unroll
            for (int ntd = 0; ntd < 4; ntd++) {
                mma_f16(oacc[ntd], phi, vh + 2 * ntd);
                mma_f16(oacc[ntd], plo, vh + 2 * ntd);
            }
        }
    }

    lsum0 += __shfl_xor_sync(0xFFFFFFFF, lsum0, 1);
    lsum0 += __shfl_xor_sync(0xFFFFFFFF, lsum0, 2);
    lsum1 += __shfl_xor_sync(0xFFFFFFFF, lsum1, 1);
    lsum1 += __shfl_xor_sync(0xFFFFFFFF, lsum1, 2);
    const float inv0 = __fdividef(1.f, lsum0);
    const float inv1 = __fdividef(1.f, lsum1);

    const size_t row0 = base + (size_t)(jr + r) * CZ;
    const size_t row1 = row0 + 8 * CZ;
#pragma unroll
    for (int ntd = 0; ntd < 4; ntd++) {
        int col = ntd * 8 + c2;
        float2 g0 = __ldg((const float2*)(g_G + row0 + col));
        float2 g1 = __ldg((const float2*)(g_G + row1 + col));
        float2 o0, o1;
        o0.x = oacc[ntd][0] * inv0 * g0.x;
        o0.y = oacc[ntd][1] * inv0 * g0.y;
        o1.x = oacc[ntd][2] * inv1 * g1.x;
        o1.y = oacc[ntd][3] * inv1 * g1.y;
        *(float2*)(g_AV + row0 + col) = o0;
        *(float2*)(g_AV + row1 + col) = o1;
    }
}

// ---------------------------------------------------------------------------
// Kernel 3: output projection, 64-row CTAs, fp16 2-term
// ---------------------------------------------------------------------------
__global__ __launch_bounds__(256, 3) void outproj_mma(const float* __restrict__ bo_,
                                                      float* __restrict__ out)
{
    extern __shared__ char sm[];
    const u32 sb = smem_u32(sm);
    const int tid = threadIdx.x, wid = tid >> 5, lane = tid & 31;
    const int wr = wid & 3, wc = wid >> 2;
    const size_t r0 = (size_t)blockIdx.x * 64;

    cp_weights(sb, OP_SB, 4, tid, 256);

    for (int p = tid; p < 4096; p += 256) {
        int row = p >> 6, c = (p & 63) << 1;
        float2 v = *(const float2*)(g_AV + (r0 + row) * CZ + c);
        u32 hh, ll;
        split_pack(v.x, v.y, hh, ll);
        u32 off = (u32)(row * TSTRIDE + c) * 2;
        *(u32*)(sm + OP_SA + off)            = hh;
        *(u32*)(sm + OP_SA + OP_AHALF + off) = ll;
    }
    CP_WAIT(0);
    __syncthreads();

    const int i_ = lane >> 3, r_ = lane & 7;
    const u32 aBase = sb + OP_SA +
        (u32)((wr * 16 + ((i_ & 1) << 3) + r_) * TSTRIDE + ((i_ >> 1) << 3)) * 2;
    const u32 bBase = sb + OP_SB +
        (u32)((wc * 64 + ((i_ >> 1) << 3) + r_) * TSTRIDE + ((i_ & 1) << 3)) * 2;

    float acc[8][4];
#pragma unroll
    for (int t = 0; t < 8; t++)
#pragma unroll
        for (int v = 0; v < 4; v++) acc[t][v] = 0.f;

    gemm_warp(acc, aBase, OP_AHALF, bBase);

    const int g = lane >> 2, tig = lane & 3;
    const size_t rowA = r0 + wr * 16 + g;
    const size_t rowB = rowA + 8;
#pragma unroll
    for (int nt = 0; nt < 8; nt++) {
        int col = wc * 64 + nt * 8 + tig * 2;
        float2 bov = __ldg((const float2*)(bo_ + col));
        *(float2*)(out + rowA * CZ + col) = make_float2(acc[nt][0] + bov.x, acc[nt][1] + bov.y);
        *(float2*)(out + rowB * CZ + col) = make_float2(acc[nt][2] + bov.x, acc[nt][3] + bov.y);
    }
}

// ---------------------------------------------------------------------------
extern "C" void kernel_launch(void* const* d_in, const int* in_sizes, int n_in,
                              void* d_out, int out_size)
{
    const float* x     = (const float*)d_in[0];
    const float* gamma = (const float*)d_in[1];
    const float* beta  = (const float*)d_in[2];
    const float* Wq    = (const float*)d_in[3];
    const float* Wk    = (const float*)d_in[4];
    const float* Wv    = (const float*)d_in[5];
    const float* Wb    = (const float*)d_in[6];
    const float* Wg    = (const float*)d_in[7];
    const float* bg    = (const float*)d_in[8];
    const float* Wo    = (const float*)d_in[9];
    const float* bo    = (const float*)d_in[10];
    float* out = (float*)d_out;

    cudaFuncSetAttribute(lnproj_mma,  cudaFuncAttributeMaxDynamicSharedMemorySize, LNP_SMEM);
    cudaFuncSetAttribute(outproj_mma, cudaFuncAttributeMaxDynamicSharedMemorySize, OP_SMEM);
    cudaFuncSetAttribute(attn_mma,    cudaFuncAttributeMaxDynamicSharedMemorySize, AT_SMEM);

    wtransform<<<5, 256>>>(Wq, Wk, Wv, Wg, Wo);
    lnproj_mma<<<RTOT / 128, 512, LNP_SMEM>>>(x, gamma, beta, Wb, bg);
    dim3 g2(NSEQ, 2 * NH);
    attn_mma<<<g2, 256, AT_SMEM>>>();
    outproj_mma<<<RTOT / 64, 256, OP_SMEM>>>(bo, out);
}

// round 9
// speedup vs baseline: 1.4209x; 1.1005x over previous
#include <cuda_runtime.h>
#include <cuda_fp16.h>
#include <math.h>

#define NSEQ 256
#define CZ   128
#define NH   4
#define HD   32
#define RTOT (NSEQ * NSEQ)

typedef unsigned int u32;
typedef unsigned long long u64;

// ---------------- global scratch ----------------
// Q single fp16 (pre-scaled); K/V single fp16; weights single fp16 transposed
__device__ __half g_Qh[(size_t)RTOT * CZ];
__device__ __half g_Kh[(size_t)RTOT * CZ];
__device__ __half g_Vh[(size_t)RTOT * CZ];
__device__ float  g_G[(size_t)RTOT * CZ];
__device__ float  g_BiasT[(size_t)NH * RTOT];
__device__ float  g_AV[(size_t)RTOT * CZ];
__device__ __half g_Wt[5][CZ * CZ];

// ---------------- helpers ----------------
__device__ __forceinline__ u32 smem_u32(const void* p) {
    u32 a;
    asm("{ .reg .u64 t; cvta.to.shared.u64 t, %1; cvt.u32.u64 %0, t; }" : "=r"(a) : "l"(p));
    return a;
}
__device__ __forceinline__ void ldsm_x4(u32* r, u32 addr) {
    asm volatile("ldmatrix.sync.aligned.m8n8.x4.shared.b16 {%0,%1,%2,%3}, [%4];"
        : "=r"(r[0]), "=r"(r[1]), "=r"(r[2]), "=r"(r[3]) : "r"(addr));
}
__device__ __forceinline__ void ldsm_x4_t(u32* r, u32 addr) {
    asm volatile("ldmatrix.sync.aligned.m8n8.x4.trans.shared.b16 {%0,%1,%2,%3}, [%4];"
        : "=r"(r[0]), "=r"(r[1]), "=r"(r[2]), "=r"(r[3]) : "r"(addr));
}
__device__ __forceinline__ void mma_f16(float* d, const u32* a, const u32* b) {
    asm volatile("mma.sync.aligned.m16n8k16.row.col.f32.f16.f16.f32 "
        "{%0,%1,%2,%3}, {%4,%5,%6,%7}, {%8,%9}, {%0,%1,%2,%3};"
        : "+f"(d[0]), "+f"(d[1]), "+f"(d[2]), "+f"(d[3])
        : "r"(a[0]), "r"(a[1]), "r"(a[2]), "r"(a[3]), "r"(b[0]), "r"(b[1]));
}
__device__ __forceinline__ u32 pack_h2(float x, float y) {
    __half2 t;
    t.x = __float2half_rn(x);
    t.y = __float2half_rn(y);
    return *(u32*)&t;
}
__device__ __forceinline__ void split_pack(float x, float y, u32& h, u32& l) {
    __half hx = __float2half_rn(x);
    __half hy = __float2half_rn(y);
    __half2 hh; hh.x = hx; hh.y = hy;
    h = *(u32*)&hh;
    l = pack_h2(x - __half2float(hx), y - __half2float(hy));
}
__device__ __forceinline__ void cp16(u32 dst, const void* src) {
    u64 g;
    asm("cvta.to.global.u64 %0, %1;" : "=l"(g) : "l"(src));
    asm volatile("cp.async.ca.shared.global [%0], [%1], 16;" :: "r"(dst), "l"(g));
}
#define CP_COMMIT() asm volatile("cp.async.commit_group;")
#define CP_WAIT(n)  asm volatile("cp.async.wait_group %0;" :: "n"(n))

#define TSTRIDE 136
#define TBUF    34816     // 128 rows * 136 * 2B

// lnproj smem: A hi|lo (69632) | B buf0 (34816) | B buf1 (34816) | Wb (2048)
#define LNP_SA   0
#define LNP_SB0  69632
#define LNP_SB1  104448
#define LNP_XS   69632
#define LNP_WB   139264
#define LNP_SMEM 141312
// outproj smem (64-row tiles)
#define OP_AHALF 17408
#define OP_SA    0
#define OP_SB    34816
#define OP_SMEM  69632

// ---------------------------------------------------------------------------
// Kernel 0: transpose weights -> fp16
// ---------------------------------------------------------------------------
__global__ void wtransform(const float* __restrict__ Wq, const float* __restrict__ Wk,
                           const float* __restrict__ Wv, const float* __restrict__ Wg,
                           const float* __restrict__ Wo)
{
    const float* W = (blockIdx.x == 0) ? Wq : (blockIdx.x == 1) ? Wk :
                     (blockIdx.x == 2) ? Wv : (blockIdx.x == 3) ? Wg : Wo;
    __half* H = g_Wt[blockIdx.x];
    for (int e = threadIdx.x; e < CZ * CZ; e += blockDim.x) {
        int n = e >> 7, c = e & 127;
        H[e] = __float2half_rn(W[c * CZ + n]);
    }
}

// ---------------------------------------------------------------------------
// GEMM warp mainloops: 16 rows x 64 cols.
// 2-term (A split hi/lo): 128 MMAs. 1-term (A hi only): 64 MMAs.
// ---------------------------------------------------------------------------
__device__ __forceinline__ void gemm_warp_2t(float acc[8][4], u32 aBase, u32 aHalf, u32 bBase)
{
#pragma unroll
    for (int ks = 0; ks < 8; ks++) {
        u32 ah[4], al[4];
        ldsm_x4(ah, aBase + ks * 32);
        ldsm_x4(al, aBase + aHalf + ks * 32);
#pragma unroll
        for (int p = 0; p < 4; p++) {
            u32 bh[4];
            ldsm_x4(bh, bBase + (u32)(p * 16 * TSTRIDE) * 2 + ks * 32);
            mma_f16(acc[2 * p],     ah, bh);
            mma_f16(acc[2 * p + 1], ah, bh + 2);
            mma_f16(acc[2 * p],     al, bh);
            mma_f16(acc[2 * p + 1], al, bh + 2);
        }
    }
}
__device__ __forceinline__ void gemm_warp_1t(float acc[8][4], u32 aBase, u32 bBase)
{
#pragma unroll
    for (int ks = 0; ks < 8; ks++) {
        u32 ah[4];
        ldsm_x4(ah, aBase + ks * 32);
#pragma unroll
        for (int p = 0; p < 4; p++) {
            u32 bh[4];
            ldsm_x4(bh, bBase + (u32)(p * 16 * TSTRIDE) * 2 + ks * 32);
            mma_f16(acc[2 * p],     ah, bh);
            mma_f16(acc[2 * p + 1], ah, bh + 2);
        }
    }
}

__device__ __forceinline__ void cp_weights(u32 sb, u32 bufOff, int m, int tid, int nthr)
{
    for (int e = tid; e < 2048; e += nthr) {
        int n = e >> 4, ch = e & 15;
        const __half* src = g_Wt[m] + n * 128 + ch * 8;
        cp16(sb + bufOff + (u32)(n * TSTRIDE + ch * 8) * 2, src);
    }
    CP_COMMIT();
}

// ---------------------------------------------------------------------------
// Kernel 1: LN + projections. Q/K/G 1-term, V 2-term. + bias projection.
// ---------------------------------------------------------------------------
__global__ __launch_bounds__(512) void lnproj_mma(const float* __restrict__ x,
                                                  const float* __restrict__ gamma,
                                                  const float* __restrict__ beta,
                                                  const float* __restrict__ Wb,
                                                  const float* __restrict__ bg)
{
    extern __shared__ char sm[];
    const u32 sb = smem_u32(sm);
    const int tid = threadIdx.x, wid = tid >> 5, lane = tid & 31;
    const int wr = wid & 7, wc = wid >> 3;
    const size_t r0 = (size_t)blockIdx.x * 128;
    float* xs  = (float*)(sm + LNP_XS);
    float* sWb = (float*)(sm + LNP_WB);

    const float4* xg = (const float4*)(x + r0 * CZ);
    for (int i = tid; i < 4096; i += 512) {
        float4 v = xg[i];
        int row = i >> 5, c = (i & 31) << 2;
        float* d = xs + row * 129 + c;
        d[0] = v.x; d[1] = v.y; d[2] = v.z; d[3] = v.w;
    }
    sWb[tid] = Wb[tid];
    __syncthreads();

    // LayerNorm: 4 threads per row, quad shuffles
    {
        int row = tid >> 2, sub = tid & 3;
        float* rp = xs + row * 129;
        float s = 0.f, s2 = 0.f;
#pragma unroll
        for (int c = sub * 32; c < sub * 32 + 32; c++) { float v = rp[c]; s += v; s2 += v * v; }
        s  += __shfl_xor_sync(0xFFFFFFFF, s, 1);
        s  += __shfl_xor_sync(0xFFFFFFFF, s, 2);
        s2 += __shfl_xor_sync(0xFFFFFFFF, s2, 1);
        s2 += __shfl_xor_sync(0xFFFFFFFF, s2, 2);
        float mu  = s * (1.f / 128.f);
        float var = s2 * (1.f / 128.f) - mu * mu;
        float inv = rsqrtf(var + 1e-5f);
#pragma unroll
        for (int c = sub * 32; c < sub * 32 + 32; c++)
            rp[c] = (rp[c] - mu) * inv * __ldg(gamma + c) + __ldg(beta + c);
    }
    __syncthreads();

    // bias projection (fp32 exact)
    {
        int row = tid >> 2, h = tid & 3;
        const float* xr = xs + row * 129;
        float s = 0.f;
#pragma unroll 8
        for (int c = 0; c < 128; c++) s += xr[c] * sWb[c * 4 + h];
        g_BiasT[(size_t)h * RTOT + r0 + row] = s;
    }
    // convert A -> split fp16 in smem
    for (int p = tid; p < 8192; p += 512) {
        int row = p >> 6, c = (p & 63) << 1;
        u32 hh, ll;
        split_pack(xs[row * 129 + c], xs[row * 129 + c + 1], hh, ll);
        u32 off = (u32)(row * TSTRIDE + c) * 2;
        *(u32*)(sm + LNP_SA + off)        = hh;
        *(u32*)(sm + LNP_SA + TBUF + off) = ll;
    }
    __syncthreads();

    cp_weights(sb, LNP_SB0, 0, tid, 512);

    const int i_ = lane >> 3, r_ = lane & 7;
    const u32 aBase = sb + LNP_SA +
        (u32)((wr * 16 + ((i_ & 1) << 3) + r_) * TSTRIDE + ((i_ >> 1) << 3)) * 2;
    const u32 bOffW = (u32)((wc * 64 + ((i_ >> 1) << 3) + r_) * TSTRIDE + ((i_ & 1) << 3)) * 2;
    const int g = lane >> 2, tig = lane & 3;
    const size_t rowA = r0 + wr * 16 + g;
    const size_t rowB = rowA + 8;

#pragma unroll
    for (int m = 0; m < 4; m++) {
        if (m < 3) cp_weights(sb, (m & 1) ? LNP_SB0 : LNP_SB1, m + 1, tid, 512);
        if (m < 3) { CP_WAIT(1); } else { CP_WAIT(0); }
        __syncthreads();

        const u32 bufOff = (m & 1) ? LNP_SB1 : LNP_SB0;
        float acc[8][4];
#pragma unroll
        for (int t = 0; t < 8; t++)
#pragma unroll
            for (int v = 0; v < 4; v++) acc[t][v] = 0.f;

        if (m == 2) gemm_warp_2t(acc, aBase, TBUF, sb + bufOff + bOffW);
        else        gemm_warp_1t(acc, aBase, sb + bufOff + bOffW);

        if (m == 0) {
            const float qs = 0.17677669529663689f;
#pragma unroll
            for (int nt = 0; nt < 8; nt++) {
                int col = wc * 64 + nt * 8 + tig * 2;
                *(u32*)(g_Qh + rowA * CZ + col) = pack_h2(acc[nt][0] * qs, acc[nt][1] * qs);
                *(u32*)(g_Qh + rowB * CZ + col) = pack_h2(acc[nt][2] * qs, acc[nt][3] * qs);
            }
        } else if (m < 3) {
            __half* O = (m == 1) ? g_Kh : g_Vh;
#pragma unroll
            for (int nt = 0; nt < 8; nt++) {
                int col = wc * 64 + nt * 8 + tig * 2;
                *(u32*)(O + rowA * CZ + col) = pack_h2(acc[nt][0], acc[nt][1]);
                *(u32*)(O + rowB * CZ + col) = pack_h2(acc[nt][2], acc[nt][3]);
            }
        } else {
#pragma unroll
            for (int nt = 0; nt < 8; nt++) {
                int col = wc * 64 + nt * 8 + tig * 2;
                float2 bgv = __ldg((const float2*)(bg + col));
                float2 oA, oB;
                oA.x = 1.f / (1.f + __expf(-(acc[nt][0] + bgv.x)));
                oA.y = 1.f / (1.f + __expf(-(acc[nt][1] + bgv.y)));
                oB.x = 1.f / (1.f + __expf(-(acc[nt][2] + bgv.x)));
                oB.y = 1.f / (1.f + __expf(-(acc[nt][3] + bgv.y)));
                *(float2*)(g_G + rowA * CZ + col) = oA;
                *(float2*)(g_G + rowB * CZ + col) = oB;
            }
        }
        __syncthreads();
    }
}

// ---------------------------------------------------------------------------
// Kernel 2: attention. QK 1-term, PV 1-term.
// Grid (256, 8): blockIdx.x = i, blockIdx.y = h*2 + jhalf. 8 warps x 16 j-rows.
// ---------------------------------------------------------------------------
#define KSTR 40
#define AT_BUF 20480
#define AT_SMEM (2 * AT_BUF)

__global__ __launch_bounds__(256, 2) void attn_mma()
{
    extern __shared__ char sm[];
    const u32 sb = smem_u32(sm);
    const int tid = threadIdx.x, wid = tid >> 5, lane = tid & 31;
    const int bi = blockIdx.x;
    const int h  = blockIdx.y >> 1;
    const int jh = blockIdx.y & 1;
    const size_t base = ((size_t)bi * NSEQ) * CZ + (size_t)h * HD;

    for (int e = tid; e < 2048; e += 256) {
        int buf = e >> 10, rem = e & 1023, k = rem >> 2, ch = rem & 3;
        const __half* src = ((buf == 0) ? g_Kh : g_Vh) + base + (size_t)k * CZ + ch * 8;
        cp16(sb + (u32)buf * AT_BUF + (u32)(k * KSTR + ch * 8) * 2, src);
    }
    CP_COMMIT();

    const int jr = jh * 128 + wid * 16;
    const int r  = lane >> 2, c2 = (lane & 3) << 1;

    u32 qh[2][4];
#pragma unroll
    for (int ks = 0; ks < 2; ks++)
#pragma unroll
        for (int reg = 0; reg < 4; reg++) {
            int row = jr + r + (reg & 1) * 8;
            int col = ks * 16 + c2 + ((reg >> 1) << 3);
            qh[ks][reg] = *(const u32*)(g_Qh + base + (size_t)row * CZ + col);
        }

    CP_WAIT(0);
    __syncthreads();

    const int i_ = lane >> 3, r_ = lane & 7;
    const int brow = ((i_ >> 1) << 3) + r_;
    const int bcol = (i_ & 1) << 3;
    const int vsel = lane >> 3, vrow = lane & 7;
    const u32 vOff = (u32)(((vsel & 1) * 8 + vrow) * KSTR + ((vsel >> 1) << 3)) * 2;

    float oacc[4][4];
#pragma unroll
    for (int t = 0; t < 4; t++)
#pragma unroll
        for (int v = 0; v < 4; v++) oacc[t][v] = 0.f;
    float lsum0 = 0.f, lsum1 = 0.f;

    const float* bias0 = g_BiasT + (size_t)h * RTOT + (size_t)(jr + r) * NSEQ;
    const float* bias1 = bias0 + 8 * NSEQ;

    for (int kc = 0; kc < 4; kc++) {
        float sacc[8][4];
#pragma unroll
        for (int t = 0; t < 8; t++)
#pragma unroll
            for (int v = 0; v < 4; v++) sacc[t][v] = 0.f;

        // ---- S = Q K^T : 1-term ----
#pragma unroll
        for (int p4 = 0; p4 < 4; p4++) {
#pragma unroll
            for (int ks = 0; ks < 2; ks++) {
                u32 kh[4];
                ldsm_x4(kh, sb + (u32)((kc * 64 + p4 * 16 + brow) * KSTR + ks * 16 + bcol) * 2);
                mma_f16(sacc[2 * p4],     qh[ks], kh);
                mma_f16(sacc[2 * p4 + 1], qh[ks], kh + 2);
            }
        }

        // ---- bias + exp (no-max; scores bounded) ----
#pragma unroll
        for (int nt = 0; nt < 8; nt++) {
            int kcol = kc * 64 + nt * 8 + c2;
            float2 b0 = __ldg((const float2*)(bias0 + kcol));
            float2 b1 = __ldg((const float2*)(bias1 + kcol));
            float p00 = __expf(sacc[nt][0] + b0.x);
            float p01 = __expf(sacc[nt][1] + b0.y);
            float p10 = __expf(sacc[nt][2] + b1.x);
            float p11 = __expf(sacc[nt][3] + b1.y);
            sacc[nt][0] = p00; sacc[nt][1] = p01;
            sacc[nt][2] = p10; sacc[nt][3] = p11;
            lsum0 += p00 + p01;
            lsum1 += p10 + p11;
        }

        // ---- O += P V : 1-term, V via trans-ldsm ----
#pragma unroll
        for (int ks2 = 0; ks2 < 4; ks2++) {
            u32 a0 = sb + AT_BUF + (u32)((kc * 64 + ks2 * 16) * KSTR) * 2 + vOff;
            u32 vh[8];
            ldsm_x4_t(vh,     a0);
            ldsm_x4_t(vh + 4, a0 + 32);
            u32 phi[4];
            {
                const float* s0 = sacc[2 * ks2];
                const float* s1 = sacc[2 * ks2 + 1];
                phi[0] = pack_h2(s0[0], s0[1]);
                phi[1] = pack_h2(s0[2], s0[3]);
                phi[2] = pack_h2(s1[0], s1[1]);
                phi[3] = pack_h2(s1[2], s1[3]);
            }
#pragma unroll
            for (int ntd = 0; ntd < 4; ntd++)
                mma_f16(oacc[ntd], phi, vh + 2 * ntd);
        }
    }

    lsum0 += __shfl_xor_sync(0xFFFFFFFF, lsum0, 1);
    lsum0 += __shfl_xor_sync(0xFFFFFFFF, lsum0, 2);
    lsum1 += __shfl_xor_sync(0xFFFFFFFF, lsum1, 1);
    lsum1 += __shfl_xor_sync(0xFFFFFFFF, lsum1, 2);
    const float inv0 = __fdividef(1.f, lsum0);
    const float inv1 = __fdividef(1.f, lsum1);

    const size_t row0 = base + (size_t)(jr + r) * CZ;
    const size_t row1 = row0 + 8 * CZ;
#pragma unroll
    for (int ntd = 0; ntd < 4; ntd++) {
        int col = ntd * 8 + c2;
        float2 g0 = __ldg((const float2*)(g_G + row0 + col));
        float2 g1 = __ldg((const float2*)(g_G + row1 + col));
        float2 o0, o1;
        o0.x = oacc[ntd][0] * inv0 * g0.x;
        o0.y = oacc[ntd][1] * inv0 * g0.y;
        o1.x = oacc[ntd][2] * inv1 * g1.x;
        o1.y = oacc[ntd][3] * inv1 * g1.y;
        *(float2*)(g_AV + row0 + col) = o0;
        *(float2*)(g_AV + row1 + col) = o1;
    }
}

// ---------------------------------------------------------------------------
// Kernel 3: output projection, 64-row CTAs, 2-term (direct output path)
// ---------------------------------------------------------------------------
__global__ __launch_bounds__(256, 3) void outproj_mma(const float* __restrict__ bo_,
                                                      float* __restrict__ out)
{
    extern __shared__ char sm[];
    const u32 sb = smem_u32(sm);
    const int tid = threadIdx.x, wid = tid >> 5, lane = tid & 31;
    const int wr = wid & 3, wc = wid >> 2;
    const size_t r0 = (size_t)blockIdx.x * 64;

    cp_weights(sb, OP_SB, 4, tid, 256);

    for (int p = tid; p < 4096; p += 256) {
        int row = p >> 6, c = (p & 63) << 1;
        float2 v = *(const float2*)(g_AV + (r0 + row) * CZ + c);
        u32 hh, ll;
        split_pack(v.x, v.y, hh, ll);
        u32 off = (u32)(row * TSTRIDE + c) * 2;
        *(u32*)(sm + OP_SA + off)            = hh;
        *(u32*)(sm + OP_SA + OP_AHALF + off) = ll;
    }
    CP_WAIT(0);
    __syncthreads();

    const int i_ = lane >> 3, r_ = lane & 7;
    const u32 aBase = sb + OP_SA +
        (u32)((wr * 16 + ((i_ & 1) << 3) + r_) * TSTRIDE + ((i_ >> 1) << 3)) * 2;
    const u32 bBase = sb + OP_SB +
        (u32)((wc * 64 + ((i_ >> 1) << 3) + r_) * TSTRIDE + ((i_ & 1) << 3)) * 2;

    float acc[8][4];
#pragma unroll
    for (int t = 0; t < 8; t++)
#pragma unroll
        for (int v = 0; v < 4; v++) acc[t][v] = 0.f;

    gemm_warp_2t(acc, aBase, OP_AHALF, bBase);

    const int g = lane >> 2, tig = lane & 3;
    const size_t rowA = r0 + wr * 16 + g;
    const size_t rowB = rowA + 8;
#pragma unroll
    for (int nt = 0; nt < 8; nt++) {
        int col = wc * 64 + nt * 8 + tig * 2;
        float2 bov = __ldg((const float2*)(bo_ + col));
        *(float2*)(out + rowA * CZ + col) = make_float2(acc[nt][0] + bov.x, acc[nt][1] + bov.y);
        *(float2*)(out + rowB * CZ + col) = make_float2(acc[nt][2] + bov.x, acc[nt][3] + bov.y);
    }
}

// ---------------------------------------------------------------------------
extern "C" void kernel_launch(void* const* d_in, const int* in_sizes, int n_in,
                              void* d_out, int out_size)
{
    const float* x     = (const float*)d_in[0];
    const float* gamma = (const float*)d_in[1];
    const float* beta  = (const float*)d_in[2];
    const float* Wq    = (const float*)d_in[3];
    const float* Wk    = (const float*)d_in[4];
    const float* Wv    = (const float*)d_in[5];
    const float* Wb    = (const float*)d_in[6];
    const float* Wg    = (const float*)d_in[7];
    const float* bg    = (const float*)d_in[8];
    const float* Wo    = (const float*)d_in[9];
    const float* bo    = (const float*)d_in[10];
    float* out = (float*)d_out;

    cudaFuncSetAttribute(lnproj_mma,  cudaFuncAttributeMaxDynamicSharedMemorySize, LNP_SMEM);
    cudaFuncSetAttribute(outproj_mma, cudaFuncAttributeMaxDynamicSharedMemorySize, OP_SMEM);
    cudaFuncSetAttribute(attn_mma,    cudaFuncAttributeMaxDynamicSharedMemorySize, AT_SMEM);

    wtransform<<<5, 256>>>(Wq, Wk, Wv, Wg, Wo);
    lnproj_mma<<<RTOT / 128, 512, LNP_SMEM>>>(x, gamma, beta, Wb, bg);
    dim3 g2(NSEQ, 2 * NH);
    attn_mma<<<g2, 256, AT_SMEM>>>();
    outproj_mma<<<RTOT / 64, 256, OP_SMEM>>>(bo, out);
}

// round 10
// speedup vs baseline: 1.7233x; 1.2128x over previous
#include <cuda_runtime.h>
#include <cuda_fp16.h>
#include <math.h>

#define NSEQ 256
#define CZ   128
#define NH   4
#define HD   32
#define RTOT (NSEQ * NSEQ)

typedef unsigned int u32;
typedef unsigned long long u64;

// ---------------- global scratch ----------------
__device__ __half g_Qh[(size_t)RTOT * CZ];   // pre-scaled
__device__ __half g_Kh[(size_t)RTOT * CZ];
__device__ __half g_Vh[(size_t)RTOT * CZ];
__device__ float  g_G[(size_t)RTOT * CZ];
__device__ float  g_BiasT[(size_t)NH * RTOT];
__device__ __half g_AVh[(size_t)RTOT * CZ];  // gated attention output, fp16
__device__ __half g_Wt[5][CZ * CZ];

// ---------------- helpers ----------------
__device__ __forceinline__ u32 smem_u32(const void* p) {
    u32 a;
    asm("{ .reg .u64 t; cvta.to.shared.u64 t, %1; cvt.u32.u64 %0, t; }" : "=r"(a) : "l"(p));
    return a;
}
__device__ __forceinline__ void ldsm_x4(u32* r, u32 addr) {
    asm volatile("ldmatrix.sync.aligned.m8n8.x4.shared.b16 {%0,%1,%2,%3}, [%4];"
        : "=r"(r[0]), "=r"(r[1]), "=r"(r[2]), "=r"(r[3]) : "r"(addr));
}
__device__ __forceinline__ void ldsm_x4_t(u32* r, u32 addr) {
    asm volatile("ldmatrix.sync.aligned.m8n8.x4.trans.shared.b16 {%0,%1,%2,%3}, [%4];"
        : "=r"(r[0]), "=r"(r[1]), "=r"(r[2]), "=r"(r[3]) : "r"(addr));
}
__device__ __forceinline__ void mma_f16(float* d, const u32* a, const u32* b) {
    asm volatile("mma.sync.aligned.m16n8k16.row.col.f32.f16.f16.f32 "
        "{%0,%1,%2,%3}, {%4,%5,%6,%7}, {%8,%9}, {%0,%1,%2,%3};"
        : "+f"(d[0]), "+f"(d[1]), "+f"(d[2]), "+f"(d[3])
        : "r"(a[0]), "r"(a[1]), "r"(a[2]), "r"(a[3]), "r"(b[0]), "r"(b[1]));
}
__device__ __forceinline__ u32 pack_h2(float x, float y) {
    __half2 t;
    t.x = __float2half_rn(x);
    t.y = __float2half_rn(y);
    return *(u32*)&t;
}
__device__ __forceinline__ void cp16(u32 dst, const void* src) {
    u64 g;
    asm("cvta.to.global.u64 %0, %1;" : "=l"(g) : "l"(src));
    asm volatile("cp.async.ca.shared.global [%0], [%1], 16;" :: "r"(dst), "l"(g));
}
#define CP_COMMIT() asm volatile("cp.async.commit_group;")
#define CP_WAIT(n)  asm volatile("cp.async.wait_group %0;" :: "n"(n))

#define TSTRIDE 136
#define TBUF    34816     // 128 rows * 136 * 2B

// lnproj smem: A (34816) | B buf0 (34816) | B buf1 (34816) | Wb (2048)
// xs fp32 (128*129*4 = 66048) overlays SB0+SB1
#define LNP_SA   0
#define LNP_SB0  34816
#define LNP_SB1  69632
#define LNP_XS   34816
#define LNP_WB   104448
#define LNP_SMEM 106496
// outproj smem (64-row tiles): A fp16 (17408) | B (34816)
#define OP_SA    0
#define OP_SB    17408
#define OP_SMEM  52224

// ---------------------------------------------------------------------------
// Kernel 0: transpose weights -> fp16
// ---------------------------------------------------------------------------
__global__ void wtransform(const float* __restrict__ Wq, const float* __restrict__ Wk,
                           const float* __restrict__ Wv, const float* __restrict__ Wg,
                           const float* __restrict__ Wo)
{
    const float* W = (blockIdx.x == 0) ? Wq : (blockIdx.x == 1) ? Wk :
                     (blockIdx.x == 2) ? Wv : (blockIdx.x == 3) ? Wg : Wo;
    __half* H = g_Wt[blockIdx.x];
    for (int e = threadIdx.x; e < CZ * CZ; e += blockDim.x) {
        int n = e >> 7, c = e & 127;
        H[e] = __float2half_rn(W[c * CZ + n]);
    }
}

// ---------------------------------------------------------------------------
// 1-term GEMM warp mainloop: 16 rows x 64 cols, 64 MMAs
// ---------------------------------------------------------------------------
__device__ __forceinline__ void gemm_warp_1t(float acc[8][4], u32 aBase, u32 bBase)
{
#pragma unroll
    for (int ks = 0; ks < 8; ks++) {
        u32 ah[4];
        ldsm_x4(ah, aBase + ks * 32);
#pragma unroll
        for (int p = 0; p < 4; p++) {
            u32 bh[4];
            ldsm_x4(bh, bBase + (u32)(p * 16 * TSTRIDE) * 2 + ks * 32);
            mma_f16(acc[2 * p],     ah, bh);
            mma_f16(acc[2 * p + 1], ah, bh + 2);
        }
    }
}

__device__ __forceinline__ void cp_weights(u32 sb, u32 bufOff, int m, int tid, int nthr)
{
    for (int e = tid; e < 2048; e += nthr) {
        int n = e >> 4, ch = e & 15;
        const __half* src = g_Wt[m] + n * 128 + ch * 8;
        cp16(sb + bufOff + (u32)(n * TSTRIDE + ch * 8) * 2, src);
    }
    CP_COMMIT();
}

// ---------------------------------------------------------------------------
// Kernel 1: LN + 4 projections (all 1-term) + bias projection (fp32 exact)
// ---------------------------------------------------------------------------
__global__ __launch_bounds__(512) void lnproj_mma(const float* __restrict__ x,
                                                  const float* __restrict__ gamma,
                                                  const float* __restrict__ beta,
                                                  const float* __restrict__ Wb,
                                                  const float* __restrict__ bg)
{
    extern __shared__ char sm[];
    const u32 sb = smem_u32(sm);
    const int tid = threadIdx.x, wid = tid >> 5, lane = tid & 31;
    const int wr = wid & 7, wc = wid >> 3;
    const size_t r0 = (size_t)blockIdx.x * 128;
    float* xs  = (float*)(sm + LNP_XS);
    float* sWb = (float*)(sm + LNP_WB);

    const float4* xg = (const float4*)(x + r0 * CZ);
    for (int i = tid; i < 4096; i += 512) {
        float4 v = xg[i];
        int row = i >> 5, c = (i & 31) << 2;
        float* d = xs + row * 129 + c;
        d[0] = v.x; d[1] = v.y; d[2] = v.z; d[3] = v.w;
    }
    sWb[tid] = Wb[tid];
    __syncthreads();

    // LayerNorm: 4 threads per row, quad shuffles
    {
        int row = tid >> 2, sub = tid & 3;
        float* rp = xs + row * 129;
        float s = 0.f, s2 = 0.f;
#pragma unroll
        for (int c = sub * 32; c < sub * 32 + 32; c++) { float v = rp[c]; s += v; s2 += v * v; }
        s  += __shfl_xor_sync(0xFFFFFFFF, s, 1);
        s  += __shfl_xor_sync(0xFFFFFFFF, s, 2);
        s2 += __shfl_xor_sync(0xFFFFFFFF, s2, 1);
        s2 += __shfl_xor_sync(0xFFFFFFFF, s2, 2);
        float mu  = s * (1.f / 128.f);
        float var = s2 * (1.f / 128.f) - mu * mu;
        float inv = rsqrtf(var + 1e-5f);
#pragma unroll
        for (int c = sub * 32; c < sub * 32 + 32; c++)
            rp[c] = (rp[c] - mu) * inv * __ldg(gamma + c) + __ldg(beta + c);
    }
    __syncthreads();

    // bias projection (fp32 exact)
    {
        int row = tid >> 2, h = tid & 3;
        const float* xr = xs + row * 129;
        float s = 0.f;
#pragma unroll 8
        for (int c = 0; c < 128; c++) s += xr[c] * sWb[c * 4 + h];
        g_BiasT[(size_t)h * RTOT + r0 + row] = s;
    }
    // convert A -> fp16 in smem (SA does not overlap xs)
    for (int p = tid; p < 8192; p += 512) {
        int row = p >> 6, c = (p & 63) << 1;
        u32 hh = pack_h2(xs[row * 129 + c], xs[row * 129 + c + 1]);
        *(u32*)(sm + LNP_SA + (u32)(row * TSTRIDE + c) * 2) = hh;
    }
    __syncthreads();   // xs consumed before weights overwrite its region

    cp_weights(sb, LNP_SB0, 0, tid, 512);

    const int i_ = lane >> 3, r_ = lane & 7;
    const u32 aBase = sb + LNP_SA +
        (u32)((wr * 16 + ((i_ & 1) << 3) + r_) * TSTRIDE + ((i_ >> 1) << 3)) * 2;
    const u32 bOffW = (u32)((wc * 64 + ((i_ >> 1) << 3) + r_) * TSTRIDE + ((i_ & 1) << 3)) * 2;
    const int g = lane >> 2, tig = lane & 3;
    const size_t rowA = r0 + wr * 16 + g;
    const size_t rowB = rowA + 8;

#pragma unroll
    for (int m = 0; m < 4; m++) {
        if (m < 3) cp_weights(sb, (m & 1) ? LNP_SB0 : LNP_SB1, m + 1, tid, 512);
        if (m < 3) { CP_WAIT(1); } else { CP_WAIT(0); }
        __syncthreads();

        const u32 bufOff = (m & 1) ? LNP_SB1 : LNP_SB0;
        float acc[8][4];
#pragma unroll
        for (int t = 0; t < 8; t++)
#pragma unroll
            for (int v = 0; v < 4; v++) acc[t][v] = 0.f;

        gemm_warp_1t(acc, aBase, sb + bufOff + bOffW);

        if (m == 0) {
            const float qs = 0.17677669529663689f;
#pragma unroll
            for (int nt = 0; nt < 8; nt++) {
                int col = wc * 64 + nt * 8 + tig * 2;
                *(u32*)(g_Qh + rowA * CZ + col) = pack_h2(acc[nt][0] * qs, acc[nt][1] * qs);
                *(u32*)(g_Qh + rowB * CZ + col) = pack_h2(acc[nt][2] * qs, acc[nt][3] * qs);
            }
        } else if (m < 3) {
            __half* O = (m == 1) ? g_Kh : g_Vh;
#pragma unroll
            for (int nt = 0; nt < 8; nt++) {
                int col = wc * 64 + nt * 8 + tig * 2;
                *(u32*)(O + rowA * CZ + col) = pack_h2(acc[nt][0], acc[nt][1]);
                *(u32*)(O + rowB * CZ + col) = pack_h2(acc[nt][2], acc[nt][3]);
            }
        } else {
#pragma unroll
            for (int nt = 0; nt < 8; nt++) {
                int col = wc * 64 + nt * 8 + tig * 2;
                float2 bgv = __ldg((const float2*)(bg + col));
                float2 oA, oB;
                oA.x = 1.f / (1.f + __expf(-(acc[nt][0] + bgv.x)));
                oA.y = 1.f / (1.f + __expf(-(acc[nt][1] + bgv.y)));
                oB.x = 1.f / (1.f + __expf(-(acc[nt][2] + bgv.x)));
                oB.y = 1.f / (1.f + __expf(-(acc[nt][3] + bgv.y)));
                *(float2*)(g_G + rowA * CZ + col) = oA;
                *(float2*)(g_G + rowB * CZ + col) = oB;
            }
        }
        __syncthreads();
    }
}

// ---------------------------------------------------------------------------
// Kernel 2: attention (QK 1-term, PV 1-term); AV written fp16
// Grid (256, 8): blockIdx.x = i, blockIdx.y = h*2 + jhalf. 8 warps x 16 j-rows.
// ---------------------------------------------------------------------------
#define KSTR 40
#define AT_BUF 20480
#define AT_SMEM (2 * AT_BUF)

__global__ __launch_bounds__(256, 2) void attn_mma()
{
    extern __shared__ char sm[];
    const u32 sb = smem_u32(sm);
    const int tid = threadIdx.x, wid = tid >> 5, lane = tid & 31;
    const int bi = blockIdx.x;
    const int h  = blockIdx.y >> 1;
    const int jh = blockIdx.y & 1;
    const size_t base = ((size_t)bi * NSEQ) * CZ + (size_t)h * HD;

    for (int e = tid; e < 2048; e += 256) {
        int buf = e >> 10, rem = e & 1023, k = rem >> 2, ch = rem & 3;
        const __half* src = ((buf == 0) ? g_Kh : g_Vh) + base + (size_t)k * CZ + ch * 8;
        cp16(sb + (u32)buf * AT_BUF + (u32)(k * KSTR + ch * 8) * 2, src);
    }
    CP_COMMIT();

    const int jr = jh * 128 + wid * 16;
    const int r  = lane >> 2, c2 = (lane & 3) << 1;

    u32 qh[2][4];
#pragma unroll
    for (int ks = 0; ks < 2; ks++)
#pragma unroll
        for (int reg = 0; reg < 4; reg++) {
            int row = jr + r + (reg & 1) * 8;
            int col = ks * 16 + c2 + ((reg >> 1) << 3);
            qh[ks][reg] = *(const u32*)(g_Qh + base + (size_t)row * CZ + col);
        }

    CP_WAIT(0);
    __syncthreads();

    const int i_ = lane >> 3, r_ = lane & 7;
    const int brow = ((i_ >> 1) << 3) + r_;
    const int bcol = (i_ & 1) << 3;
    const int vsel = lane >> 3, vrow = lane & 7;
    const u32 vOff = (u32)(((vsel & 1) * 8 + vrow) * KSTR + ((vsel >> 1) << 3)) * 2;

    float oacc[4][4];
#pragma unroll
    for (int t = 0; t < 4; t++)
#pragma unroll
        for (int v = 0; v < 4; v++) oacc[t][v] = 0.f;
    float lsum0 = 0.f, lsum1 = 0.f;

    const float* bias0 = g_BiasT + (size_t)h * RTOT + (size_t)(jr + r) * NSEQ;
    const float* bias1 = bias0 + 8 * NSEQ;

    for (int kc = 0; kc < 4; kc++) {
        float sacc[8][4];
#pragma unroll
        for (int t = 0; t < 8; t++)
#pragma unroll
            for (int v = 0; v < 4; v++) sacc[t][v] = 0.f;

#pragma unroll
        for (int p4 = 0; p4 < 4; p4++) {
#pragma unroll
            for (int ks = 0; ks < 2; ks++) {
                u32 kh[4];
                ldsm_x4(kh, sb + (u32)((kc * 64 + p4 * 16 + brow) * KSTR + ks * 16 + bcol) * 2);
                mma_f16(sacc[2 * p4],     qh[ks], kh);
                mma_f16(sacc[2 * p4 + 1], qh[ks], kh + 2);
            }
        }

#pragma unroll
        for (int nt = 0; nt < 8; nt++) {
            int kcol = kc * 64 + nt * 8 + c2;
            float2 b0 = __ldg((const float2*)(bias0 + kcol));
            float2 b1 = __ldg((const float2*)(bias1 + kcol));
            float p00 = __expf(sacc[nt][0] + b0.x);
            float p01 = __expf(sacc[nt][1] + b0.y);
            float p10 = __expf(sacc[nt][2] + b1.x);
            float p11 = __expf(sacc[nt][3] + b1.y);
            sacc[nt][0] = p00; sacc[nt][1] = p01;
            sacc[nt][2] = p10; sacc[nt][3] = p11;
            lsum0 += p00 + p01;
            lsum1 += p10 + p11;
        }

#pragma unroll
        for (int ks2 = 0; ks2 < 4; ks2++) {
            u32 a0 = sb + AT_BUF + (u32)((kc * 64 + ks2 * 16) * KSTR) * 2 + vOff;
            u32 vh[8];
            ldsm_x4_t(vh,     a0);
            ldsm_x4_t(vh + 4, a0 + 32);
            u32 phi[4];
            {
                const float* s0 = sacc[2 * ks2];
                const float* s1 = sacc[2 * ks2 + 1];
                phi[0] = pack_h2(s0[0], s0[1]);
                phi[1] = pack_h2(s0[2], s0[3]);
                phi[2] = pack_h2(s1[0], s1[1]);
                phi[3] = pack_h2(s1[2], s1[3]);
            }
#pragma unroll
            for (int ntd = 0; ntd < 4; ntd++)
                mma_f16(oacc[ntd], phi, vh + 2 * ntd);
        }
    }

    lsum0 += __shfl_xor_sync(0xFFFFFFFF, lsum0, 1);
    lsum0 += __shfl_xor_sync(0xFFFFFFFF, lsum0, 2);
    lsum1 += __shfl_xor_sync(0xFFFFFFFF, lsum1, 1);
    lsum1 += __shfl_xor_sync(0xFFFFFFFF, lsum1, 2);
    const float inv0 = __fdividef(1.f, lsum0);
    const float inv1 = __fdividef(1.f, lsum1);

    const size_t row0 = base + (size_t)(jr + r) * CZ;
    const size_t row1 = row0 + 8 * CZ;
#pragma unroll
    for (int ntd = 0; ntd < 4; ntd++) {
        int col = ntd * 8 + c2;
        float2 g0 = __ldg((const float2*)(g_G + row0 + col));
        float2 g1 = __ldg((const float2*)(g_G + row1 + col));
        *(u32*)(g_AVh + row0 + col) = pack_h2(oacc[ntd][0] * inv0 * g0.x,
                                              oacc[ntd][1] * inv0 * g0.y);
        *(u32*)(g_AVh + row1 + col) = pack_h2(oacc[ntd][2] * inv1 * g1.x,
                                              oacc[ntd][3] * inv1 * g1.y);
    }
}

// ---------------------------------------------------------------------------
// Kernel 3: output projection, 64-row CTAs, 1-term; pure cp.async staging
// ---------------------------------------------------------------------------
__global__ __launch_bounds__(256, 3) void outproj_mma(const float* __restrict__ bo_,
                                                      float* __restrict__ out)
{
    extern __shared__ char sm[];
    const u32 sb = smem_u32(sm);
    const int tid = threadIdx.x, wid = tid >> 5, lane = tid & 31;
    const int wr = wid & 3, wc = wid >> 2;
    const size_t r0 = (size_t)blockIdx.x * 64;

    // A tile: 64 rows x 128 fp16 via cp.async (no conversion)
    for (int e = tid; e < 1024; e += 256) {
        int row = e >> 4, ch = e & 15;
        const __half* src = g_AVh + (r0 + row) * CZ + ch * 8;
        cp16(sb + OP_SA + (u32)(row * TSTRIDE + ch * 8) * 2, src);
    }
    CP_COMMIT();
    cp_weights(sb, OP_SB, 4, tid, 256);
    CP_WAIT(0);
    __syncthreads();

    const int i_ = lane >> 3, r_ = lane & 7;
    const u32 aBase = sb + OP_SA +
        (u32)((wr * 16 + ((i_ & 1) << 3) + r_) * TSTRIDE + ((i_ >> 1) << 3)) * 2;
    const u32 bBase = sb + OP_SB +
        (u32)((wc * 64 + ((i_ >> 1) << 3) + r_) * TSTRIDE + ((i_ & 1) << 3)) * 2;

    float acc[8][4];
#pragma unroll
    for (int t = 0; t < 8; t++)
#pragma unroll
        for (int v = 0; v < 4; v++) acc[t][v] = 0.f;

    gemm_warp_1t(acc, aBase, bBase);

    const int g = lane >> 2, tig = lane & 3;
    const size_t rowA = r0 + wr * 16 + g;
    const size_t rowB = rowA + 8;
#pragma unroll
    for (int nt = 0; nt < 8; nt++) {
        int col = wc * 64 + nt * 8 + tig * 2;
        float2 bov = __ldg((const float2*)(bo_ + col));
        *(float2*)(out + rowA * CZ + col) = make_float2(acc[nt][0] + bov.x, acc[nt][1] + bov.y);
        *(float2*)(out + rowB * CZ + col) = make_float2(acc[nt][2] + bov.x, acc[nt][3] + bov.y);
    }
}

// ---------------------------------------------------------------------------
extern "C" void kernel_launch(void* const* d_in, const int* in_sizes, int n_in,
                              void* d_out, int out_size)
{
    const float* x     = (const float*)d_in[0];
    const float* gamma = (const float*)d_in[1];
    const float* beta  = (const float*)d_in[2];
    const float* Wq    = (const float*)d_in[3];
    const float* Wk    = (const float*)d_in[4];
    const float* Wv    = (const float*)d_in[5];
    const float* Wb    = (const float*)d_in[6];
    const float* Wg    = (const float*)d_in[7];
    const float* bg    = (const float*)d_in[8];
    const float* Wo    = (const float*)d_in[9];
    const float* bo    = (const float*)d_in[10];
    float* out = (float*)d_out;

    cudaFuncSetAttribute(lnproj_mma,  cudaFuncAttributeMaxDynamicSharedMemorySize, LNP_SMEM);
    cudaFuncSetAttribute(outproj_mma, cudaFuncAttributeMaxDynamicSharedMemorySize, OP_SMEM);
    cudaFuncSetAttribute(attn_mma,    cudaFuncAttributeMaxDynamicSharedMemorySize, AT_SMEM);

    wtransform<<<5, 256>>>(Wq, Wk, Wv, Wg, Wo);
    lnproj_mma<<<RTOT / 128, 512, LNP_SMEM>>>(x, gamma, beta, Wb, bg);
    dim3 g2(NSEQ, 2 * NH);
    attn_mma<<<g2, 256, AT_SMEM>>>();
    outproj_mma<<<RTOT / 64, 256, OP_SMEM>>>(bo, out);
}

// round 11
// speedup vs baseline: 1.8655x; 1.0825x over previous
#include <cuda_runtime.h>
#include <cuda_fp16.h>
#include <math.h>

#define NSEQ 256
#define CZ   128
#define NH   4
#define HD   32
#define RTOT (NSEQ * NSEQ)

typedef unsigned int u32;
typedef unsigned long long u64;

// ---------------- global scratch ----------------
__device__ __half g_Qh[(size_t)RTOT * CZ];   // pre-scaled
__device__ __half g_Kh[(size_t)RTOT * CZ];
__device__ __half g_Vh[(size_t)RTOT * CZ];
__device__ float  g_G[(size_t)RTOT * CZ];
__device__ float  g_BiasT[(size_t)NH * RTOT];
__device__ __half g_AVh[(size_t)RTOT * CZ];
__device__ __half g_Wt[5][CZ * CZ];

// ---------------- helpers ----------------
__device__ __forceinline__ u32 smem_u32(const void* p) {
    u32 a;
    asm("{ .reg .u64 t; cvta.to.shared.u64 t, %1; cvt.u32.u64 %0, t; }" : "=r"(a) : "l"(p));
    return a;
}
__device__ __forceinline__ void ldsm_x4(u32* r, u32 addr) {
    asm volatile("ldmatrix.sync.aligned.m8n8.x4.shared.b16 {%0,%1,%2,%3}, [%4];"
        : "=r"(r[0]), "=r"(r[1]), "=r"(r[2]), "=r"(r[3]) : "r"(addr));
}
__device__ __forceinline__ void ldsm_x4_t(u32* r, u32 addr) {
    asm volatile("ldmatrix.sync.aligned.m8n8.x4.trans.shared.b16 {%0,%1,%2,%3}, [%4];"
        : "=r"(r[0]), "=r"(r[1]), "=r"(r[2]), "=r"(r[3]) : "r"(addr));
}
__device__ __forceinline__ void mma_f16(float* d, const u32* a, const u32* b) {
    asm volatile("mma.sync.aligned.m16n8k16.row.col.f32.f16.f16.f32 "
        "{%0,%1,%2,%3}, {%4,%5,%6,%7}, {%8,%9}, {%0,%1,%2,%3};"
        : "+f"(d[0]), "+f"(d[1]), "+f"(d[2]), "+f"(d[3])
        : "r"(a[0]), "r"(a[1]), "r"(a[2]), "r"(a[3]), "r"(b[0]), "r"(b[1]));
}
__device__ __forceinline__ u32 pack_h2(float x, float y) {
    __half2 t;
    t.x = __float2half_rn(x);
    t.y = __float2half_rn(y);
    return *(u32*)&t;
}
__device__ __forceinline__ void cp16(u32 dst, const void* src) {
    u64 g;
    asm("cvta.to.global.u64 %0, %1;" : "=l"(g) : "l"(src));
    asm volatile("cp.async.ca.shared.global [%0], [%1], 16;" :: "r"(dst), "l"(g));
}
#define CP_COMMIT() asm volatile("cp.async.commit_group;")
#define CP_WAIT(n)  asm volatile("cp.async.wait_group %0;" :: "n"(n))

#define TSTRIDE 136
#define TBUF    34816     // 128 rows * 136 * 2B

// lnproj smem: A (34816) | B buf0 | B buf1 | Wb; xs fp32 overlays SB0+SB1
#define LNP_SA   0
#define LNP_SB0  34816
#define LNP_SB1  69632
#define LNP_XS   34816
#define LNP_WB   104448
#define LNP_SMEM 106496
// outproj smem (128-row tiles): A fp16 (34816) | B (34816)
#define OP_SA    0
#define OP_SB    34816
#define OP_SMEM  69632

// ---------------------------------------------------------------------------
// Kernel 0: transpose weights -> fp16
// ---------------------------------------------------------------------------
__global__ void wtransform(const float* __restrict__ Wq, const float* __restrict__ Wk,
                           const float* __restrict__ Wv, const float* __restrict__ Wg,
                           const float* __restrict__ Wo)
{
    const float* W = (blockIdx.x == 0) ? Wq : (blockIdx.x == 1) ? Wk :
                     (blockIdx.x == 2) ? Wv : (blockIdx.x == 3) ? Wg : Wo;
    __half* H = g_Wt[blockIdx.x];
    for (int e = threadIdx.x; e < CZ * CZ; e += blockDim.x) {
        int n = e >> 7, c = e & 127;
        H[e] = __float2half_rn(W[c * CZ + n]);
    }
}

// ---------------------------------------------------------------------------
// 64x32 warp-tile GEMM mainloop: per ks, 4 A-ldsm + 2 B-ldsm -> 16 MMAs
// acc[ai*4+ni][4], ai = 16-row subtile (0..3), ni = 8-col subtile (0..3)
// ---------------------------------------------------------------------------
__device__ __forceinline__ void gemm_warp64(float acc[16][4], u32 aBase, u32 bBase)
{
#pragma unroll
    for (int ks = 0; ks < 8; ks++) {
        u32 a0[4], a1[4], a2[4], a3[4], b0[4], b1[4];
        ldsm_x4(a0, aBase + ks * 32);
        ldsm_x4(a1, aBase + (u32)(16 * TSTRIDE) * 2 + ks * 32);
        ldsm_x4(a2, aBase + (u32)(32 * TSTRIDE) * 2 + ks * 32);
        ldsm_x4(a3, aBase + (u32)(48 * TSTRIDE) * 2 + ks * 32);
        ldsm_x4(b0, bBase + ks * 32);
        ldsm_x4(b1, bBase + (u32)(16 * TSTRIDE) * 2 + ks * 32);
        mma_f16(acc[0],  a0, b0); mma_f16(acc[1],  a0, b0 + 2);
        mma_f16(acc[2],  a0, b1); mma_f16(acc[3],  a0, b1 + 2);
        mma_f16(acc[4],  a1, b0); mma_f16(acc[5],  a1, b0 + 2);
        mma_f16(acc[6],  a1, b1); mma_f16(acc[7],  a1, b1 + 2);
        mma_f16(acc[8],  a2, b0); mma_f16(acc[9],  a2, b0 + 2);
        mma_f16(acc[10], a2, b1); mma_f16(acc[11], a2, b1 + 2);
        mma_f16(acc[12], a3, b0); mma_f16(acc[13], a3, b0 + 2);
        mma_f16(acc[14], a3, b1); mma_f16(acc[15], a3, b1 + 2);
    }
}

__device__ __forceinline__ void cp_weights(u32 sb, u32 bufOff, int m, int tid, int nthr)
{
    for (int e = tid; e < 2048; e += nthr) {
        int n = e >> 4, ch = e & 15;
        const __half* src = g_Wt[m] + n * 128 + ch * 8;
        cp16(sb + bufOff + (u32)(n * TSTRIDE + ch * 8) * 2, src);
    }
    CP_COMMIT();
}

// ---------------------------------------------------------------------------
// Kernel 1: LN + 4 projections (1-term) + bias projection. 256 threads, 8 warps
// warp grid 2 (rows) x 4 (cols): warp tile 64 x 32
// ---------------------------------------------------------------------------
__global__ __launch_bounds__(256, 2) void lnproj_mma(const float* __restrict__ x,
                                                     const float* __restrict__ gamma,
                                                     const float* __restrict__ beta,
                                                     const float* __restrict__ Wb,
                                                     const float* __restrict__ bg)
{
    extern __shared__ char sm[];
    const u32 sb = smem_u32(sm);
    const int tid = threadIdx.x, wid = tid >> 5, lane = tid & 31;
    const int wr = wid & 1, wc = wid >> 1;
    const size_t r0 = (size_t)blockIdx.x * 128;
    float* xs  = (float*)(sm + LNP_XS);
    float* sWb = (float*)(sm + LNP_WB);

    const float4* xg = (const float4*)(x + r0 * CZ);
    for (int i = tid; i < 4096; i += 256) {
        float4 v = xg[i];
        int row = i >> 5, c = (i & 31) << 2;
        float* d = xs + row * 129 + c;
        d[0] = v.x; d[1] = v.y; d[2] = v.z; d[3] = v.w;
    }
    sWb[tid] = Wb[tid];
    sWb[tid + 256] = Wb[tid + 256];
    __syncthreads();

    // LayerNorm: 2 threads per row
    {
        int row = tid >> 1, sub = tid & 1;
        float* rp = xs + row * 129;
        float s = 0.f, s2 = 0.f;
#pragma unroll
        for (int c = sub * 64; c < sub * 64 + 64; c++) { float v = rp[c]; s += v; s2 += v * v; }
        s  += __shfl_xor_sync(0xFFFFFFFF, s, 1);
        s2 += __shfl_xor_sync(0xFFFFFFFF, s2, 1);
        float mu  = s * (1.f / 128.f);
        float var = s2 * (1.f / 128.f) - mu * mu;
        float inv = rsqrtf(var + 1e-5f);
#pragma unroll
        for (int c = sub * 64; c < sub * 64 + 64; c++)
            rp[c] = (rp[c] - mu) * inv * __ldg(gamma + c) + __ldg(beta + c);
    }
    __syncthreads();

    // bias projection (fp32 exact): 2 outputs per thread
    for (int o = tid; o < 512; o += 256) {
        int row = o >> 2, h = o & 3;
        const float* xr = xs + row * 129;
        float s = 0.f;
#pragma unroll 8
        for (int c = 0; c < 128; c++) s += xr[c] * sWb[c * 4 + h];
        g_BiasT[(size_t)h * RTOT + r0 + row] = s;
    }
    // convert A -> fp16 in smem
    for (int p = tid; p < 8192; p += 256) {
        int row = p >> 6, c = (p & 63) << 1;
        u32 hh = pack_h2(xs[row * 129 + c], xs[row * 129 + c + 1]);
        *(u32*)(sm + LNP_SA + (u32)(row * TSTRIDE + c) * 2) = hh;
    }
    __syncthreads();   // xs consumed before weights overwrite its region

    cp_weights(sb, LNP_SB0, 0, tid, 256);

    const int i_ = lane >> 3, r_ = lane & 7;
    const u32 aBase = sb + LNP_SA +
        (u32)((wr * 64 + ((i_ & 1) << 3) + r_) * TSTRIDE + ((i_ >> 1) << 3)) * 2;
    const u32 bOffW = (u32)((wc * 32 + ((i_ >> 1) << 3) + r_) * TSTRIDE + ((i_ & 1) << 3)) * 2;
    const int g = lane >> 2, tig = lane & 3;

#pragma unroll
    for (int m = 0; m < 4; m++) {
        if (m < 3) cp_weights(sb, (m & 1) ? LNP_SB0 : LNP_SB1, m + 1, tid, 256);
        if (m < 3) { CP_WAIT(1); } else { CP_WAIT(0); }
        __syncthreads();

        const u32 bufOff = (m & 1) ? LNP_SB1 : LNP_SB0;
        float acc[16][4];
#pragma unroll
        for (int t = 0; t < 16; t++)
#pragma unroll
            for (int v = 0; v < 4; v++) acc[t][v] = 0.f;

        gemm_warp64(acc, aBase, sb + bufOff + bOffW);

        if (m == 0) {
            const float qs = 0.17677669529663689f;
#pragma unroll
            for (int ai = 0; ai < 4; ai++) {
                size_t rowA = r0 + wr * 64 + ai * 16 + g;
                size_t rowB = rowA + 8;
#pragma unroll
                for (int ni = 0; ni < 4; ni++) {
                    int col = wc * 32 + ni * 8 + tig * 2;
                    float* a = acc[ai * 4 + ni];
                    *(u32*)(g_Qh + rowA * CZ + col) = pack_h2(a[0] * qs, a[1] * qs);
                    *(u32*)(g_Qh + rowB * CZ + col) = pack_h2(a[2] * qs, a[3] * qs);
                }
            }
        } else if (m < 3) {
            __half* O = (m == 1) ? g_Kh : g_Vh;
#pragma unroll
            for (int ai = 0; ai < 4; ai++) {
                size_t rowA = r0 + wr * 64 + ai * 16 + g;
                size_t rowB = rowA + 8;
#pragma unroll
                for (int ni = 0; ni < 4; ni++) {
                    int col = wc * 32 + ni * 8 + tig * 2;
                    float* a = acc[ai * 4 + ni];
                    *(u32*)(O + rowA * CZ + col) = pack_h2(a[0], a[1]);
                    *(u32*)(O + rowB * CZ + col) = pack_h2(a[2], a[3]);
                }
            }
        } else {
#pragma unroll
            for (int ai = 0; ai < 4; ai++) {
                size_t rowA = r0 + wr * 64 + ai * 16 + g;
                size_t rowB = rowA + 8;
#pragma unroll
                for (int ni = 0; ni < 4; ni++) {
                    int col = wc * 32 + ni * 8 + tig * 2;
                    float2 bgv = __ldg((const float2*)(bg + col));
                    float* a = acc[ai * 4 + ni];
                    float2 oA, oB;
                    oA.x = 1.f / (1.f + __expf(-(a[0] + bgv.x)));
                    oA.y = 1.f / (1.f + __expf(-(a[1] + bgv.y)));
                    oB.x = 1.f / (1.f + __expf(-(a[2] + bgv.x)));
                    oB.y = 1.f / (1.f + __expf(-(a[3] + bgv.y)));
                    *(float2*)(g_G + rowA * CZ + col) = oA;
                    *(float2*)(g_G + rowB * CZ + col) = oB;
                }
            }
        }
        __syncthreads();
    }
}

// ---------------------------------------------------------------------------
// Kernel 2: attention. Grid (256, 4): one CTA = full (i,h). 8 warps x 32 j.
// 32-k chunks: QK 4 ldsm/16 MMA, PV 4 ldsm/16 MMA.
// ---------------------------------------------------------------------------
#define KSTR 40
#define AT_BUF 20480
#define AT_SMEM (2 * AT_BUF)

__global__ __launch_bounds__(256, 2) void attn_mma()
{
    extern __shared__ char sm[];
    const u32 sb = smem_u32(sm);
    const int tid = threadIdx.x, wid = tid >> 5, lane = tid & 31;
    const int bi = blockIdx.x;
    const int h  = blockIdx.y;
    const size_t base = ((size_t)bi * NSEQ) * CZ + (size_t)h * HD;

    for (int e = tid; e < 2048; e += 256) {
        int buf = e >> 10, rem = e & 1023, k = rem >> 2, ch = rem & 3;
        const __half* src = ((buf == 0) ? g_Kh : g_Vh) + base + (size_t)k * CZ + ch * 8;
        cp16(sb + (u32)buf * AT_BUF + (u32)(k * KSTR + ch * 8) * 2, src);
    }
    CP_COMMIT();

    const int jr = wid * 32;
    const int r  = lane >> 2, c2 = (lane & 3) << 1;

    // Q fragments: 2 a-tiles x 2 ks
    u32 qh[2][2][4];
#pragma unroll
    for (int a = 0; a < 2; a++)
#pragma unroll
        for (int ks = 0; ks < 2; ks++)
#pragma unroll
            for (int reg = 0; reg < 4; reg++) {
                int row = jr + a * 16 + r + (reg & 1) * 8;
                int col = ks * 16 + c2 + ((reg >> 1) << 3);
                qh[a][ks][reg] = *(const u32*)(g_Qh + base + (size_t)row * CZ + col);
            }

    CP_WAIT(0);
    __syncthreads();

    const int i_ = lane >> 3, r_ = lane & 7;
    const int brow = ((i_ >> 1) << 3) + r_;
    const int bcol = (i_ & 1) << 3;
    const int vsel = lane >> 3, vrow = lane & 7;
    const u32 vOff = (u32)(((vsel & 1) * 8 + vrow) * KSTR + ((vsel >> 1) << 3)) * 2;

    float oacc[2][4][4];
#pragma unroll
    for (int a = 0; a < 2; a++)
#pragma unroll
        for (int t = 0; t < 4; t++)
#pragma unroll
            for (int v = 0; v < 4; v++) oacc[a][t][v] = 0.f;
    float lsum[2][2] = {{0.f, 0.f}, {0.f, 0.f}};

    const float* biasH = g_BiasT + (size_t)h * RTOT;

    for (int kc = 0; kc < 8; kc++) {
        float sacc[2][4][4];
#pragma unroll
        for (int a = 0; a < 2; a++)
#pragma unroll
            for (int t = 0; t < 4; t++)
#pragma unroll
                for (int v = 0; v < 4; v++) sacc[a][t][v] = 0.f;

        // ---- S = Q K^T over this 32-k chunk ----
#pragma unroll
        for (int ks = 0; ks < 2; ks++) {
            u32 k0[4], k1[4];
            u32 ka = sb + (u32)((kc * 32 + brow) * KSTR + ks * 16 + bcol) * 2;
            ldsm_x4(k0, ka);
            ldsm_x4(k1, ka + (u32)(16 * KSTR) * 2);
#pragma unroll
            for (int a = 0; a < 2; a++) {
                mma_f16(sacc[a][0], qh[a][ks], k0);
                mma_f16(sacc[a][1], qh[a][ks], k0 + 2);
                mma_f16(sacc[a][2], qh[a][ks], k1);
                mma_f16(sacc[a][3], qh[a][ks], k1 + 2);
            }
        }

        // ---- bias + exp (no-max; scores bounded) ----
#pragma unroll
        for (int a = 0; a < 2; a++) {
            const float* b0p = biasH + (size_t)(jr + a * 16 + r) * NSEQ;
            const float* b1p = b0p + 8 * NSEQ;
#pragma unroll
            for (int nt = 0; nt < 4; nt++) {
                int kcol = kc * 32 + nt * 8 + c2;
                float2 b0 = __ldg((const float2*)(b0p + kcol));
                float2 b1 = __ldg((const float2*)(b1p + kcol));
                float p00 = __expf(sacc[a][nt][0] + b0.x);
                float p01 = __expf(sacc[a][nt][1] + b0.y);
                float p10 = __expf(sacc[a][nt][2] + b1.x);
                float p11 = __expf(sacc[a][nt][3] + b1.y);
                sacc[a][nt][0] = p00; sacc[a][nt][1] = p01;
                sacc[a][nt][2] = p10; sacc[a][nt][3] = p11;
                lsum[a][0] += p00 + p01;
                lsum[a][1] += p10 + p11;
            }
        }

        // ---- O += P V over this chunk (2 x 16-k steps) ----
#pragma unroll
        for (int ks2 = 0; ks2 < 2; ks2++) {
            u32 va = sb + AT_BUF + (u32)((kc * 32 + ks2 * 16) * KSTR) * 2 + vOff;
            u32 vh[8];
            ldsm_x4_t(vh,     va);
            ldsm_x4_t(vh + 4, va + 32);
#pragma unroll
            for (int a = 0; a < 2; a++) {
                u32 phi[4];
                const float* s0 = sacc[a][2 * ks2];
                const float* s1 = sacc[a][2 * ks2 + 1];
                phi[0] = pack_h2(s0[0], s0[1]);
                phi[1] = pack_h2(s0[2], s0[3]);
                phi[2] = pack_h2(s1[0], s1[1]);
                phi[3] = pack_h2(s1[2], s1[3]);
#pragma unroll
                for (int ntd = 0; ntd < 4; ntd++)
                    mma_f16(oacc[a][ntd], phi, vh + 2 * ntd);
            }
        }
    }

#pragma unroll
    for (int a = 0; a < 2; a++)
#pragma unroll
        for (int c = 0; c < 2; c++) {
            lsum[a][c] += __shfl_xor_sync(0xFFFFFFFF, lsum[a][c], 1);
            lsum[a][c] += __shfl_xor_sync(0xFFFFFFFF, lsum[a][c], 2);
        }

#pragma unroll
    for (int a = 0; a < 2; a++) {
        const float inv0 = __fdividef(1.f, lsum[a][0]);
        const float inv1 = __fdividef(1.f, lsum[a][1]);
        const size_t row0 = base + (size_t)(jr + a * 16 + r) * CZ;
        const size_t row1 = row0 + 8 * CZ;
#pragma unroll
        for (int ntd = 0; ntd < 4; ntd++) {
            int col = ntd * 8 + c2;
            float2 g0 = __ldg((const float2*)(g_G + row0 + col));
            float2 g1 = __ldg((const float2*)(g_G + row1 + col));
            *(u32*)(g_AVh + row0 + col) = pack_h2(oacc[a][ntd][0] * inv0 * g0.x,
                                                  oacc[a][ntd][1] * inv0 * g0.y);
            *(u32*)(g_AVh + row1 + col) = pack_h2(oacc[a][ntd][2] * inv1 * g1.x,
                                                  oacc[a][ntd][3] * inv1 * g1.y);
        }
    }
}

// ---------------------------------------------------------------------------
// Kernel 3: output projection, 128-row CTAs, 8 warps (64x32 tiles), 1-term
// ---------------------------------------------------------------------------
__global__ __launch_bounds__(256, 2) void outproj_mma(const float* __restrict__ bo_,
                                                      float* __restrict__ out)
{
    extern __shared__ char sm[];
    const u32 sb = smem_u32(sm);
    const int tid = threadIdx.x, wid = tid >> 5, lane = tid & 31;
    const int wr = wid & 1, wc = wid >> 1;
    const size_t r0 = (size_t)blockIdx.x * 128;

    // A tile: 128 rows x 128 fp16 via cp.async
    for (int e = tid; e < 2048; e += 256) {
        int row = e >> 4, ch = e & 15;
        const __half* src = g_AVh + (r0 + row) * CZ + ch * 8;
        cp16(sb + OP_SA + (u32)(row * TSTRIDE + ch * 8) * 2, src);
    }
    CP_COMMIT();
    cp_weights(sb, OP_SB, 4, tid, 256);
    CP_WAIT(0);
    __syncthreads();

    const int i_ = lane >> 3, r_ = lane & 7;
    const u32 aBase = sb + OP_SA +
        (u32)((wr * 64 + ((i_ & 1) << 3) + r_) * TSTRIDE + ((i_ >> 1) << 3)) * 2;
    const u32 bBase = sb + OP_SB +
        (u32)((wc * 32 + ((i_ >> 1) << 3) + r_) * TSTRIDE + ((i_ & 1) << 3)) * 2;

    float acc[16][4];
#pragma unroll
    for (int t = 0; t < 16; t++)
#pragma unroll
        for (int v = 0; v < 4; v++) acc[t][v] = 0.f;

    gemm_warp64(acc, aBase, bBase);

    const int g = lane >> 2, tig = lane & 3;
#pragma unroll
    for (int ai = 0; ai < 4; ai++) {
        size_t rowA = r0 + wr * 64 + ai * 16 + g;
        size_t rowB = rowA + 8;
#pragma unroll
        for (int ni = 0; ni < 4; ni++) {
            int col = wc * 32 + ni * 8 + tig * 2;
            float2 bov = __ldg((const float2*)(bo_ + col));
            float* a = acc[ai * 4 + ni];
            *(float2*)(out + rowA * CZ + col) = make_float2(a[0] + bov.x, a[1] + bov.y);
            *(float2*)(out + rowB * CZ + col) = make_float2(a[2] + bov.x, a[3] + bov.y);
        }
    }
}

// ---------------------------------------------------------------------------
extern "C" void kernel_launch(void* const* d_in, const int* in_sizes, int n_in,
                              void* d_out, int out_size)
{
    const float* x     = (const float*)d_in[0];
    const float* gamma = (const float*)d_in[1];
    const float* beta  = (const float*)d_in[2];
    const float* Wq    = (const float*)d_in[3];
    const float* Wk    = (const float*)d_in[4];
    const float* Wv    = (const float*)d_in[5];
    const float* Wb    = (const float*)d_in[6];
    const float* Wg    = (const float*)d_in[7];
    const float* bg    = (const float*)d_in[8];
    const float* Wo    = (const float*)d_in[9];
    const float* bo    = (const float*)d_in[10];
    float* out = (float*)d_out;

    cudaFuncSetAttribute(lnproj_mma,  cudaFuncAttributeMaxDynamicSharedMemorySize, LNP_SMEM);
    cudaFuncSetAttribute(outproj_mma, cudaFuncAttributeMaxDynamicSharedMemorySize, OP_SMEM);
    cudaFuncSetAttribute(attn_mma,    cudaFuncAttributeMaxDynamicSharedMemorySize, AT_SMEM);

    wtransform<<<5, 256>>>(Wq, Wk, Wv, Wg, Wo);
    lnproj_mma<<<RTOT / 128, 256, LNP_SMEM>>>(x, gamma, beta, Wb, bg);
    dim3 g2(NSEQ, NH);
    attn_mma<<<g2, 256, AT_SMEM>>>();
    outproj_mma<<<RTOT / 128, 256, OP_SMEM>>>(bo, out);
}